// round 1
// baseline (speedup 1.0000x reference)
#include <cuda_runtime.h>

#define NB 8
#define NT 1024
#define ND 1024
#define NH 16
#define HD 64

// Scratch: Q,K,V in [B,H,T,hd] (head-major for attention), attn output in
// [B,T,H*hd] = [B,T,D] (row-major, feeds final GEMM directly).
__device__ float g_Q[NB * NH * NT * HD];
__device__ float g_K[NB * NH * NT * HD];
__device__ float g_V[NB * NH * NT * HD];
__device__ float g_Ao[NB * NT * ND];

// ---------------------------------------------------------------------------
// C[m,n] = sum_k A[m,k] * W[n,k] (+ bias[n])
// A: [M,K] row-major, W: [N,K] row-major (i.e. x @ W^T).
// HEADMAJOR=1: scatter output to [B,H,T,hd] layout (m=b*T+t, n=h*64+d).
// BM=BN=128, BK=8, 256 threads, 8x8 per thread.
// ---------------------------------------------------------------------------
template <int HEADMAJOR>
__global__ __launch_bounds__(256) void sgemm_nt(
    const float* __restrict__ A, const float* __restrict__ W,
    const float* __restrict__ bias, float* __restrict__ C,
    int M, int N, int K)
{
    __shared__ float As[8][128];
    __shared__ float Bs[8][128];

    const int tid = threadIdx.x;
    const int tx = tid & 15;        // 0..15 -> 8 output cols each
    const int ty = tid >> 4;        // 0..15 -> 8 output rows each
    const int brow = blockIdx.y * 128;
    const int bcol = blockIdx.x * 128;

    float acc[8][8];
#pragma unroll
    for (int i = 0; i < 8; i++)
#pragma unroll
        for (int j = 0; j < 8; j++) acc[i][j] = 0.0f;

    const int lrow = tid >> 1;          // 0..127
    const int lk = (tid & 1) * 4;       // 0 or 4
    const float* Ag = A + (size_t)(brow + lrow) * K + lk;
    const float* Wg = W + (size_t)(bcol + lrow) * K + lk;

    for (int k0 = 0; k0 < K; k0 += 8) {
        float4 av = *(const float4*)(Ag + k0);
        float4 wv = *(const float4*)(Wg + k0);
        __syncthreads();
        As[lk + 0][lrow] = av.x; As[lk + 1][lrow] = av.y;
        As[lk + 2][lrow] = av.z; As[lk + 3][lrow] = av.w;
        Bs[lk + 0][lrow] = wv.x; Bs[lk + 1][lrow] = wv.y;
        Bs[lk + 2][lrow] = wv.z; Bs[lk + 3][lrow] = wv.w;
        __syncthreads();
#pragma unroll
        for (int k = 0; k < 8; k++) {
            float a[8], b[8];
            *(float4*)&a[0] = *(const float4*)&As[k][ty * 8];
            *(float4*)&a[4] = *(const float4*)&As[k][ty * 8 + 4];
            *(float4*)&b[0] = *(const float4*)&Bs[k][tx * 8];
            *(float4*)&b[4] = *(const float4*)&Bs[k][tx * 8 + 4];
#pragma unroll
            for (int i = 0; i < 8; i++)
#pragma unroll
                for (int j = 0; j < 8; j++)
                    acc[i][j] = fmaf(a[i], b[j], acc[i][j]);
        }
    }

#pragma unroll
    for (int i = 0; i < 8; i++) {
        const int m = brow + ty * 8 + i;
#pragma unroll
        for (int j = 0; j < 8; j++) {
            const int n = bcol + tx * 8 + j;
            float v = acc[i][j];
            if (bias) v += bias[n];
            if (HEADMAJOR) {
                const int b = m >> 10;       // T = 1024
                const int t = m & 1023;
                const int h = n >> 6;        // hd = 64
                const int d = n & 63;
                C[(((size_t)(b * NH + h) * NT + t) << 6) + d] = v;
            } else {
                C[(size_t)m * N + n] = v;
            }
        }
    }
}

// ---------------------------------------------------------------------------
// Causal flash attention. One block = one (b,h) x 128-query tile.
// 128 threads, one query per thread; q-row and o-accumulator in registers;
// K/V streamed through smem in 64-key tiles. Additive -1e9 mask == exact
// zero after exp in fp32, so masked keys are simply skipped.
// ---------------------------------------------------------------------------
__global__ __launch_bounds__(128) void attn_kernel(
    const float* __restrict__ Q, const float* __restrict__ K,
    const float* __restrict__ V, float* __restrict__ O)
{
    const int qt = blockIdx.x;
    const int bh = blockIdx.y;
    const int b = bh >> 4;          // H = 16
    const int h = bh & 15;

    const float* Qp = Q + (size_t)bh * NT * HD;
    const float* Kp = K + (size_t)bh * NT * HD;
    const float* Vp = V + (size_t)bh * NT * HD;

    const int tid = threadIdx.x;
    const int qi = qt * 128 + tid;   // this thread's query index

    float q[64], o[64];
#pragma unroll
    for (int d = 0; d < 64; d += 4) {
        float4 t = *(const float4*)(Qp + (size_t)qi * HD + d);
        q[d] = t.x; q[d + 1] = t.y; q[d + 2] = t.z; q[d + 3] = t.w;
    }
#pragma unroll
    for (int d = 0; d < 64; d++) o[d] = 0.0f;

    float mrun = -3.0e38f;
    float l = 0.0f;

    __shared__ float Ks[64 * 64];
    __shared__ float Vs[64 * 64];

    const int nkt = 2 * qt + 2;      // key tiles covering [0, qt*128+128)
    for (int kt = 0; kt < nkt; kt++) {
        __syncthreads();
        const float4* kg = (const float4*)(Kp + kt * 4096);
        const float4* vg = (const float4*)(Vp + kt * 4096);
        float4* ks4 = (float4*)Ks;
        float4* vs4 = (float4*)Vs;
#pragma unroll
        for (int i = 0; i < 8; i++) {
            ks4[i * 128 + tid] = kg[i * 128 + tid];
            vs4[i * 128 + tid] = vg[i * 128 + tid];
        }
        __syncthreads();

        int kmax = qi - kt * 64 + 1;          // causal bound within tile
        if (kmax > 64) kmax = 64;
        for (int j = 0; j < kmax; j++) {
            const float4* kr = (const float4*)(Ks + j * 64);
            float s0 = 0.f, s1 = 0.f, s2 = 0.f, s3 = 0.f;
#pragma unroll
            for (int d4 = 0; d4 < 16; d4 += 4) {
                float4 k0 = kr[d4 + 0], k1 = kr[d4 + 1];
                float4 k2 = kr[d4 + 2], k3 = kr[d4 + 3];
                s0 = fmaf(q[d4 * 4 + 0], k0.x, s0); s0 = fmaf(q[d4 * 4 + 1], k0.y, s0);
                s0 = fmaf(q[d4 * 4 + 2], k0.z, s0); s0 = fmaf(q[d4 * 4 + 3], k0.w, s0);
                s1 = fmaf(q[d4 * 4 + 4], k1.x, s1); s1 = fmaf(q[d4 * 4 + 5], k1.y, s1);
                s1 = fmaf(q[d4 * 4 + 6], k1.z, s1); s1 = fmaf(q[d4 * 4 + 7], k1.w, s1);
                s2 = fmaf(q[d4 * 4 + 8], k2.x, s2); s2 = fmaf(q[d4 * 4 + 9], k2.y, s2);
                s2 = fmaf(q[d4 * 4 + 10], k2.z, s2); s2 = fmaf(q[d4 * 4 + 11], k2.w, s2);
                s3 = fmaf(q[d4 * 4 + 12], k3.x, s3); s3 = fmaf(q[d4 * 4 + 13], k3.y, s3);
                s3 = fmaf(q[d4 * 4 + 14], k3.z, s3); s3 = fmaf(q[d4 * 4 + 15], k3.w, s3);
            }
            float s = ((s0 + s1) + (s2 + s3)) * 0.125f;  // hd^-0.5 fold

            if (s > mrun) {                    // rare after warmup
                const float corr = __expf(mrun - s);
                l *= corr;
#pragma unroll
                for (int d = 0; d < 64; d++) o[d] *= corr;
                mrun = s;
            }
            const float p = __expf(s - mrun);
            l += p;
            const float4* vr = (const float4*)(Vs + j * 64);
#pragma unroll
            for (int d4 = 0; d4 < 16; d4++) {
                float4 vv = vr[d4];
                o[d4 * 4 + 0] = fmaf(p, vv.x, o[d4 * 4 + 0]);
                o[d4 * 4 + 1] = fmaf(p, vv.y, o[d4 * 4 + 1]);
                o[d4 * 4 + 2] = fmaf(p, vv.z, o[d4 * 4 + 2]);
                o[d4 * 4 + 3] = fmaf(p, vv.w, o[d4 * 4 + 3]);
            }
        }
    }

    const float inv = 1.0f / l;
    float* Op = O + (((size_t)(b * NT + qi) * NH + h) << 6);  // [B,T,H,hd]
#pragma unroll
    for (int d = 0; d < 64; d += 4) {
        float4 t;
        t.x = o[d] * inv; t.y = o[d + 1] * inv;
        t.z = o[d + 2] * inv; t.w = o[d + 3] * inv;
        *(float4*)(Op + d) = t;
    }
}

// ---------------------------------------------------------------------------
// Inputs (metadata order): x, mask, Wq, bq, Wk, Wv, bv, Wo, bo
// ---------------------------------------------------------------------------
extern "C" void kernel_launch(void* const* d_in, const int* in_sizes, int n_in,
                              void* d_out, int out_size)
{
    const float* x  = (const float*)d_in[0];
    // d_in[1] = mask: encoded structurally (causal skip), not read.
    const float* Wq = (const float*)d_in[2];
    const float* bq = (const float*)d_in[3];
    const float* Wk = (const float*)d_in[4];
    const float* Wv = (const float*)d_in[5];
    const float* bv = (const float*)d_in[6];
    const float* Wo = (const float*)d_in[7];
    const float* bo = (const float*)d_in[8];
    float* out = (float*)d_out;

    float *Qp, *Kp, *Vp, *Ap;
    cudaGetSymbolAddress((void**)&Qp, g_Q);
    cudaGetSymbolAddress((void**)&Kp, g_K);
    cudaGetSymbolAddress((void**)&Vp, g_V);
    cudaGetSymbolAddress((void**)&Ap, g_Ao);

    const int M = NB * NT;                 // 8192
    dim3 gemm_grid(ND / 128, M / 128);     // (8, 64)

    sgemm_nt<1><<<gemm_grid, 256>>>(x, Wq, bq,      Qp, M, ND, ND);
    sgemm_nt<1><<<gemm_grid, 256>>>(x, Wk, nullptr, Kp, M, ND, ND);
    sgemm_nt<1><<<gemm_grid, 256>>>(x, Wv, bv,      Vp, M, ND, ND);

    attn_kernel<<<dim3(NT / 128, NB * NH), 128>>>(Qp, Kp, Vp, Ap);

    sgemm_nt<0><<<gemm_grid, 256>>>(Ap, Wo, bo, out, M, ND, ND);
}

// round 3
// speedup vs baseline: 1.5842x; 1.5842x over previous
#include <cuda_runtime.h>
#include <cuda_bf16.h>
#include <cstdint>

#define NB 8
#define NT 1024
#define ND 1024
#define NH 16
#define HD 64

// ---------------- scratch (device globals; no allocation allowed) ----------
__device__ float g_Q[NB * NH * NT * HD];
__device__ float g_K[NB * NH * NT * HD];
__device__ float g_V[NB * NH * NT * HD];
__device__ float g_Ao[NB * NT * ND];

__device__ __nv_bfloat16 g_xh[NB * NT * ND], g_xl[NB * NT * ND];
__device__ __nv_bfloat16 g_ah[NB * NT * ND], g_al[NB * NT * ND];
__device__ __nv_bfloat16 g_wqh[ND * ND], g_wql[ND * ND];
__device__ __nv_bfloat16 g_wkh[ND * ND], g_wkl[ND * ND];
__device__ __nv_bfloat16 g_wvh[ND * ND], g_wvl[ND * ND];
__device__ __nv_bfloat16 g_woh[ND * ND], g_wol[ND * ND];

__device__ __forceinline__ uint32_t smem_to_u32(const void* p) {
    uint32_t a;
    asm("{ .reg .u64 t; cvta.to.shared.u64 t, %1; cvt.u32.u64 %0, t; }"
        : "=r"(a) : "l"(p));
    return a;
}

// ---------------- bf16 split conversion ------------------------------------
__global__ __launch_bounds__(256) void split_kernel(
    const float* __restrict__ src, __nv_bfloat16* __restrict__ hi,
    __nv_bfloat16* __restrict__ lo, int n4)
{
    int i = blockIdx.x * 256 + threadIdx.x;
    if (i >= n4) return;
    float4 v = ((const float4*)src)[i];
    __nv_bfloat16 h0 = __float2bfloat16_rn(v.x);
    __nv_bfloat16 h1 = __float2bfloat16_rn(v.y);
    __nv_bfloat16 h2 = __float2bfloat16_rn(v.z);
    __nv_bfloat16 h3 = __float2bfloat16_rn(v.w);
    __nv_bfloat16 l0 = __float2bfloat16_rn(v.x - __bfloat162float(h0));
    __nv_bfloat16 l1 = __float2bfloat16_rn(v.y - __bfloat162float(h1));
    __nv_bfloat16 l2 = __float2bfloat16_rn(v.z - __bfloat162float(h2));
    __nv_bfloat16 l3 = __float2bfloat16_rn(v.w - __bfloat162float(h3));
    ((__nv_bfloat162*)hi)[2 * i + 0] = __halves2bfloat162(h0, h1);
    ((__nv_bfloat162*)hi)[2 * i + 1] = __halves2bfloat162(h2, h3);
    ((__nv_bfloat162*)lo)[2 * i + 0] = __halves2bfloat162(l0, l1);
    ((__nv_bfloat162*)lo)[2 * i + 1] = __halves2bfloat162(l2, l3);
}

// ---------------- HMMA split-bf16 GEMM -------------------------------------
// C[m,n] = sum_k A[m,k]*W[n,k] (+bias[n]); K-major both sides.
// CTA tile 128x128; 8 warps (2m x 4n); warp tile 64x32.
// mma.sync m16n8k16 row.col f32.bf16.bf16.f32, 3-pass hi/lo split.
// smem: per stage 4 tiles (Ah,Al,Bh,Bl), each 128 rows x 16 bf16, row
// stride 48B (pad) -> 6144B/tile, 24576B/stage, 2 stages = 48KB.
#define KSTEP 16
#define NKT (ND / KSTEP)          // 64
#define TILE_B 6144
#define STAGE_B 24576
#define GEMM_SMEM (2 * STAGE_B)

__device__ __forceinline__ void ldsm4(uint32_t* r, uint32_t addr) {
    asm volatile("ldmatrix.sync.aligned.m8n8.x4.shared.b16 {%0,%1,%2,%3}, [%4];"
                 : "=r"(r[0]), "=r"(r[1]), "=r"(r[2]), "=r"(r[3]) : "r"(addr));
}
__device__ __forceinline__ void mma16816(float* d, const uint32_t* a,
                                         uint32_t b0, uint32_t b1) {
    asm volatile(
        "mma.sync.aligned.m16n8k16.row.col.f32.bf16.bf16.f32 "
        "{%0,%1,%2,%3}, {%4,%5,%6,%7}, {%8,%9}, {%0,%1,%2,%3};"
        : "+f"(d[0]), "+f"(d[1]), "+f"(d[2]), "+f"(d[3])
        : "r"(a[0]), "r"(a[1]), "r"(a[2]), "r"(a[3]), "r"(b0), "r"(b1));
}

template <int HEADMAJOR>
__global__ __launch_bounds__(256, 1) void gemm_hmma(
    const __nv_bfloat16* __restrict__ Ah, const __nv_bfloat16* __restrict__ Al,
    const __nv_bfloat16* __restrict__ Bh, const __nv_bfloat16* __restrict__ Bl,
    const float* __restrict__ bias, float* __restrict__ C)
{
    extern __shared__ char smem[];
    const uint32_t sb = smem_to_u32(smem);
    const int tid = threadIdx.x;
    const int wid = tid >> 5;
    const int lane = tid & 31;
    const int m0 = (wid >> 2) * 64;       // warp m offset in CTA tile
    const int n0 = (wid & 3) * 32;        // warp n offset
    const int brow = blockIdx.y * 128;
    const int bcol = blockIdx.x * 128;

    float acc[4][4][4];
#pragma unroll
    for (int i = 0; i < 4; i++)
#pragma unroll
        for (int j = 0; j < 4; j++)
#pragma unroll
            for (int r = 0; r < 4; r++) acc[i][j][r] = 0.0f;

    const __nv_bfloat16* srcs[4] = {Ah, Al, Bh, Bl};

    auto load_stage = [&](int stage, int kt) {
#pragma unroll
        for (int i = 0; i < 4; i++) {
            const int c = i * 256 + tid;          // 1024 16B-chunks/stage
            const int tile = c >> 8;              // 0..3
            const int w = c & 255;
            const int row = w >> 1;               // 0..127
            const int half = w & 1;               // 16B half of 32B row
            const uint32_t dst = sb + stage * STAGE_B + tile * TILE_B
                               + row * 48 + half * 16;
            const int row0 = (tile < 2) ? brow : bcol;
            const size_t src = __cvta_generic_to_global(
                srcs[tile] + (size_t)(row0 + row) * ND + kt * KSTEP + half * 8);
            asm volatile("cp.async.cg.shared.global [%0], [%1], 16;"
                         :: "r"(dst), "l"(src) : "memory");
        }
        asm volatile("cp.async.commit_group;" ::: "memory");
    };

    load_stage(0, 0);

    // ldmatrix address components (byte offsets within a tile)
    const uint32_t a_row = lane & 15;                  // rows 0..15 pattern
    const uint32_t a_coff = (lane >> 4) << 4;          // k half: 0 or 16B
    const uint32_t b_row = (lane & 7) + (((lane >> 4) & 1) << 3);
    const uint32_t b_coff = ((lane >> 3) & 1) << 4;

    for (int kt = 0; kt < NKT; kt++) {
        const int stage = kt & 1;
        if (kt + 1 < NKT) {
            load_stage(stage ^ 1, kt + 1);
            asm volatile("cp.async.wait_group 1;" ::: "memory");
        } else {
            asm volatile("cp.async.wait_group 0;" ::: "memory");
        }
        __syncthreads();

        const uint32_t base = sb + stage * STAGE_B;
        uint32_t ah[4][4], al[4][4], bh[2][4], bl[2][4];
#pragma unroll
        for (int mi = 0; mi < 4; mi++) {
            const uint32_t addr = base + (m0 + mi * 16 + a_row) * 48 + a_coff;
            ldsm4(ah[mi], addr);
            ldsm4(al[mi], addr + TILE_B);
        }
#pragma unroll
        for (int nj = 0; nj < 2; nj++) {
            const uint32_t addr = base + 2 * TILE_B
                                + (n0 + nj * 16 + b_row) * 48 + b_coff;
            ldsm4(bh[nj], addr);
            ldsm4(bl[nj], addr + TILE_B);
        }
#pragma unroll
        for (int mi = 0; mi < 4; mi++)
#pragma unroll
            for (int ni = 0; ni < 4; ni++) {
                const int j = ni >> 1, r = (ni & 1) * 2;
                mma16816(acc[mi][ni], ah[mi], bh[j][r], bh[j][r + 1]);
                mma16816(acc[mi][ni], ah[mi], bl[j][r], bl[j][r + 1]);
                mma16816(acc[mi][ni], al[mi], bh[j][r], bh[j][r + 1]);
            }
        __syncthreads();
    }

    // Epilogue: acc tile (mi,ni): rows m0+mi*16+lane/4 (+8), cols n0+ni*8+2*(lane%4)
#pragma unroll
    for (int mi = 0; mi < 4; mi++) {
#pragma unroll
        for (int ni = 0; ni < 4; ni++) {
            const int mA = brow + m0 + mi * 16 + (lane >> 2);
            const int c = bcol + n0 + ni * 8 + ((lane & 3) << 1);
            float2 v0, v1;
            v0.x = acc[mi][ni][0]; v0.y = acc[mi][ni][1];
            v1.x = acc[mi][ni][2]; v1.y = acc[mi][ni][3];
            if (bias) {
                const float2 bv = *(const float2*)(bias + c);
                v0.x += bv.x; v0.y += bv.y;
                v1.x += bv.x; v1.y += bv.y;
            }
            if (HEADMAJOR) {
                const int h = c >> 6, d = c & 63;
                const int b0_ = mA >> 10, t0 = mA & 1023;
                const int mB = mA + 8;
                const int b1_ = mB >> 10, t1 = mB & 1023;
                *(float2*)&C[(((size_t)(b0_ * NH + h) * NT + t0) << 6) + d] = v0;
                *(float2*)&C[(((size_t)(b1_ * NH + h) * NT + t1) << 6) + d] = v1;
            } else {
                *(float2*)&C[(size_t)mA * ND + c] = v0;
                *(float2*)&C[(size_t)(mA + 8) * ND + c] = v1;
            }
        }
    }
}

// ---------------- causal flash attention (unchanged, proven) ---------------
__global__ __launch_bounds__(128) void attn_kernel(
    const float* __restrict__ Q, const float* __restrict__ K,
    const float* __restrict__ V, float* __restrict__ O)
{
    const int qt = blockIdx.x;
    const int bh = blockIdx.y;
    const int b = bh >> 4;
    const int h = bh & 15;

    const float* Qp = Q + (size_t)bh * NT * HD;
    const float* Kp = K + (size_t)bh * NT * HD;
    const float* Vp = V + (size_t)bh * NT * HD;

    const int tid = threadIdx.x;
    const int qi = qt * 128 + tid;

    float q[64], o[64];
#pragma unroll
    for (int d = 0; d < 64; d += 4) {
        float4 t = *(const float4*)(Qp + (size_t)qi * HD + d);
        q[d] = t.x; q[d + 1] = t.y; q[d + 2] = t.z; q[d + 3] = t.w;
    }
#pragma unroll
    for (int d = 0; d < 64; d++) o[d] = 0.0f;

    float mrun = -3.0e38f;
    float l = 0.0f;

    __shared__ float Ks[64 * 64];
    __shared__ float Vs[64 * 64];

    const int nkt = 2 * qt + 2;
    for (int kt = 0; kt < nkt; kt++) {
        __syncthreads();
        const float4* kg = (const float4*)(Kp + kt * 4096);
        const float4* vg = (const float4*)(Vp + kt * 4096);
        float4* ks4 = (float4*)Ks;
        float4* vs4 = (float4*)Vs;
#pragma unroll
        for (int i = 0; i < 8; i++) {
            ks4[i * 128 + tid] = kg[i * 128 + tid];
            vs4[i * 128 + tid] = vg[i * 128 + tid];
        }
        __syncthreads();

        int kmax = qi - kt * 64 + 1;
        if (kmax > 64) kmax = 64;
        for (int j = 0; j < kmax; j++) {
            const float4* kr = (const float4*)(Ks + j * 64);
            float s0 = 0.f, s1 = 0.f, s2 = 0.f, s3 = 0.f;
#pragma unroll
            for (int d4 = 0; d4 < 16; d4 += 4) {
                float4 k0 = kr[d4 + 0], k1 = kr[d4 + 1];
                float4 k2 = kr[d4 + 2], k3 = kr[d4 + 3];
                s0 = fmaf(q[d4 * 4 + 0], k0.x, s0); s0 = fmaf(q[d4 * 4 + 1], k0.y, s0);
                s0 = fmaf(q[d4 * 4 + 2], k0.z, s0); s0 = fmaf(q[d4 * 4 + 3], k0.w, s0);
                s1 = fmaf(q[d4 * 4 + 4], k1.x, s1); s1 = fmaf(q[d4 * 4 + 5], k1.y, s1);
                s1 = fmaf(q[d4 * 4 + 6], k1.z, s1); s1 = fmaf(q[d4 * 4 + 7], k1.w, s1);
                s2 = fmaf(q[d4 * 4 + 8], k2.x, s2); s2 = fmaf(q[d4 * 4 + 9], k2.y, s2);
                s2 = fmaf(q[d4 * 4 + 10], k2.z, s2); s2 = fmaf(q[d4 * 4 + 11], k2.w, s2);
                s3 = fmaf(q[d4 * 4 + 12], k3.x, s3); s3 = fmaf(q[d4 * 4 + 13], k3.y, s3);
                s3 = fmaf(q[d4 * 4 + 14], k3.z, s3); s3 = fmaf(q[d4 * 4 + 15], k3.w, s3);
            }
            float s = ((s0 + s1) + (s2 + s3)) * 0.125f;

            if (s > mrun) {
                const float corr = __expf(mrun - s);
                l *= corr;
#pragma unroll
                for (int d = 0; d < 64; d++) o[d] *= corr;
                mrun = s;
            }
            const float p = __expf(s - mrun);
            l += p;
            const float4* vr = (const float4*)(Vs + j * 64);
#pragma unroll
            for (int d4 = 0; d4 < 16; d4++) {
                float4 vv = vr[d4];
                o[d4 * 4 + 0] = fmaf(p, vv.x, o[d4 * 4 + 0]);
                o[d4 * 4 + 1] = fmaf(p, vv.y, o[d4 * 4 + 1]);
                o[d4 * 4 + 2] = fmaf(p, vv.z, o[d4 * 4 + 2]);
                o[d4 * 4 + 3] = fmaf(p, vv.w, o[d4 * 4 + 3]);
            }
        }
    }

    const float inv = 1.0f / l;
    float* Op = O + (((size_t)(b * NT + qi) * NH + h) << 6);
#pragma unroll
    for (int d = 0; d < 64; d += 4) {
        float4 t;
        t.x = o[d] * inv; t.y = o[d + 1] * inv;
        t.z = o[d + 2] * inv; t.w = o[d + 3] * inv;
        *(float4*)(Op + d) = t;
    }
}

// ---------------------------------------------------------------------------
// Inputs (metadata order): x, mask, Wq, bq, Wk, Wv, bv, Wo, bo
// ---------------------------------------------------------------------------
extern "C" void kernel_launch(void* const* d_in, const int* in_sizes, int n_in,
                              void* d_out, int out_size)
{
    const float* x  = (const float*)d_in[0];
    const float* Wq = (const float*)d_in[2];
    const float* bq = (const float*)d_in[3];
    const float* Wk = (const float*)d_in[4];
    const float* Wv = (const float*)d_in[5];
    const float* bv = (const float*)d_in[6];
    const float* Wo = (const float*)d_in[7];
    const float* bo = (const float*)d_in[8];
    float* out = (float*)d_out;

    float *Qp, *Kp, *Vp, *Ap;
    cudaGetSymbolAddress((void**)&Qp, g_Q);
    cudaGetSymbolAddress((void**)&Kp, g_K);
    cudaGetSymbolAddress((void**)&Vp, g_V);
    cudaGetSymbolAddress((void**)&Ap, g_Ao);

    __nv_bfloat16 *xh, *xl, *ah, *al;
    __nv_bfloat16 *wqh, *wql, *wkh, *wkl, *wvh, *wvl, *woh, *wol;
    cudaGetSymbolAddress((void**)&xh, g_xh);   cudaGetSymbolAddress((void**)&xl, g_xl);
    cudaGetSymbolAddress((void**)&ah, g_ah);   cudaGetSymbolAddress((void**)&al, g_al);
    cudaGetSymbolAddress((void**)&wqh, g_wqh); cudaGetSymbolAddress((void**)&wql, g_wql);
    cudaGetSymbolAddress((void**)&wkh, g_wkh); cudaGetSymbolAddress((void**)&wkl, g_wkl);
    cudaGetSymbolAddress((void**)&wvh, g_wvh); cudaGetSymbolAddress((void**)&wvl, g_wvl);
    cudaGetSymbolAddress((void**)&woh, g_woh); cudaGetSymbolAddress((void**)&wol, g_wol);

    const int M = NB * NT;                   // 8192
    const int xn4 = M * ND / 4;
    const int wn4 = ND * ND / 4;

    split_kernel<<<(xn4 + 255) / 256, 256>>>(x, xh, xl, xn4);
    split_kernel<<<(wn4 + 255) / 256, 256>>>(Wq, wqh, wql, wn4);
    split_kernel<<<(wn4 + 255) / 256, 256>>>(Wk, wkh, wkl, wn4);
    split_kernel<<<(wn4 + 255) / 256, 256>>>(Wv, wvh, wvl, wn4);
    split_kernel<<<(wn4 + 255) / 256, 256>>>(Wo, woh, wol, wn4);

    dim3 gemm_grid(ND / 128, M / 128);       // (8, 64)
    gemm_hmma<1><<<gemm_grid, 256, GEMM_SMEM>>>(xh, xl, wqh, wql, bq,      Qp);
    gemm_hmma<1><<<gemm_grid, 256, GEMM_SMEM>>>(xh, xl, wkh, wkl, nullptr, Kp);
    gemm_hmma<1><<<gemm_grid, 256, GEMM_SMEM>>>(xh, xl, wvh, wvl, bv,      Vp);

    attn_kernel<<<dim3(NT / 128, NB * NH), 128>>>(Qp, Kp, Vp, Ap);

    split_kernel<<<(xn4 + 255) / 256, 256>>>(Ap, ah, al, xn4);
    gemm_hmma<0><<<gemm_grid, 256, GEMM_SMEM>>>(ah, al, woh, wol, bo, out);
}

// round 4
// speedup vs baseline: 3.8497x; 2.4300x over previous
#include <cuda_runtime.h>
#include <cuda_bf16.h>
#include <cstdint>

#define NB 8
#define NT 1024
#define ND 1024
#define NH 16
#define HD 64

// ---------------- scratch (device globals; no allocation allowed) ----------
__device__ __nv_bfloat16 g_xh[NB * NT * ND], g_xl[NB * NT * ND];
__device__ __nv_bfloat16 g_qh[NB * NH * NT * HD], g_ql[NB * NH * NT * HD];
__device__ __nv_bfloat16 g_kh[NB * NH * NT * HD], g_kl[NB * NH * NT * HD];
__device__ __nv_bfloat16 g_vth[NB * NH * NT * HD], g_vtl[NB * NH * NT * HD];
__device__ __nv_bfloat16 g_aoh[NB * NT * ND], g_aol[NB * NT * ND];
__device__ __nv_bfloat16 g_wqh[ND * ND], g_wql[ND * ND];
__device__ __nv_bfloat16 g_wkh[ND * ND], g_wkl[ND * ND];
__device__ __nv_bfloat16 g_wvh[ND * ND], g_wvl[ND * ND];
__device__ __nv_bfloat16 g_woh[ND * ND], g_wol[ND * ND];

__device__ __forceinline__ uint32_t smem_to_u32(const void* p) {
    uint32_t a;
    asm("{ .reg .u64 t; cvta.to.shared.u64 t, %1; cvt.u32.u64 %0, t; }"
        : "=r"(a) : "l"(p));
    return a;
}
__device__ __forceinline__ void ldsm4(uint32_t* r, uint32_t addr) {
    asm volatile("ldmatrix.sync.aligned.m8n8.x4.shared.b16 {%0,%1,%2,%3}, [%4];"
                 : "=r"(r[0]), "=r"(r[1]), "=r"(r[2]), "=r"(r[3]) : "r"(addr));
}
__device__ __forceinline__ void mma16816(float* d, const uint32_t* a,
                                         uint32_t b0, uint32_t b1) {
    asm volatile(
        "mma.sync.aligned.m16n8k16.row.col.f32.bf16.bf16.f32 "
        "{%0,%1,%2,%3}, {%4,%5,%6,%7}, {%8,%9}, {%0,%1,%2,%3};"
        : "+f"(d[0]), "+f"(d[1]), "+f"(d[2]), "+f"(d[3])
        : "r"(a[0]), "r"(a[1]), "r"(a[2]), "r"(a[3]), "r"(b0), "r"(b1));
}
__device__ __forceinline__ void cpa16(uint32_t dst, const void* gsrc) {
    asm volatile("cp.async.cg.shared.global [%0], [%1], 16;"
                 :: "r"(dst), "l"(__cvta_generic_to_global(gsrc)) : "memory");
}
__device__ __forceinline__ uint32_t sw128(uint32_t off) {
    return off ^ ((off >> 3) & 0x70);
}
// split two fp32 into packed bf16x2 hi + lo
__device__ __forceinline__ void split2(float a, float b, uint32_t& h, uint32_t& l) {
    __nv_bfloat16 ha = __float2bfloat16_rn(a), hb = __float2bfloat16_rn(b);
    __nv_bfloat16 la = __float2bfloat16_rn(a - __bfloat162float(ha));
    __nv_bfloat16 lb = __float2bfloat16_rn(b - __bfloat162float(hb));
    __nv_bfloat162 hh = __halves2bfloat162(ha, hb);
    __nv_bfloat162 ll = __halves2bfloat162(la, lb);
    h = *reinterpret_cast<uint32_t*>(&hh);
    l = *reinterpret_cast<uint32_t*>(&ll);
}

// ---------------- bf16 split conversion ------------------------------------
__global__ __launch_bounds__(256) void split_kernel(
    const float* __restrict__ src, __nv_bfloat16* __restrict__ hi,
    __nv_bfloat16* __restrict__ lo, int n4)
{
    int i = blockIdx.x * 256 + threadIdx.x;
    if (i >= n4) return;
    float4 v = ((const float4*)src)[i];
    uint32_t h0, l0, h1, l1;
    split2(v.x, v.y, h0, l0);
    split2(v.z, v.w, h1, l1);
    ((uint32_t*)hi)[2 * i + 0] = h0;
    ((uint32_t*)hi)[2 * i + 1] = h1;
    ((uint32_t*)lo)[2 * i + 0] = l0;
    ((uint32_t*)lo)[2 * i + 1] = l1;
}

// ---------------- HMMA split-bf16 GEMM -------------------------------------
// C[m,n] = sum_k A[m,k]*W[n,k] (+bias[n]); K-major both sides.
// MODE 0: fp32 out [M,ND].  MODE 1: bf16 h/l out, head-major [b,h,t,d].
// MODE 2: bf16 h/l out, per-head transposed [b,h,d,t]  (V for attention).
#define KSTEP 16
#define NKT (ND / KSTEP)
#define TILE_B 6144
#define STAGE_B 24576
#define GEMM_SMEM (2 * STAGE_B)

template <int MODE>
__global__ __launch_bounds__(256, 1) void gemm_hmma(
    const __nv_bfloat16* __restrict__ Ah, const __nv_bfloat16* __restrict__ Al,
    const __nv_bfloat16* __restrict__ Bh, const __nv_bfloat16* __restrict__ Bl,
    const float* __restrict__ bias, float* __restrict__ C,
    __nv_bfloat16* __restrict__ Ch, __nv_bfloat16* __restrict__ Cl)
{
    extern __shared__ char smem[];
    const uint32_t sb = smem_to_u32(smem);
    const int tid = threadIdx.x;
    const int wid = tid >> 5;
    const int lane = tid & 31;
    const int m0 = (wid >> 2) * 64;
    const int n0 = (wid & 3) * 32;
    const int brow = blockIdx.y * 128;
    const int bcol = blockIdx.x * 128;

    float acc[4][4][4];
#pragma unroll
    for (int i = 0; i < 4; i++)
#pragma unroll
        for (int j = 0; j < 4; j++)
#pragma unroll
            for (int r = 0; r < 4; r++) acc[i][j][r] = 0.0f;

    const __nv_bfloat16* srcs[4] = {Ah, Al, Bh, Bl};

    auto load_stage = [&](int stage, int kt) {
#pragma unroll
        for (int i = 0; i < 4; i++) {
            const int c = i * 256 + tid;
            const int tile = c >> 8;
            const int w = c & 255;
            const int row = w >> 1;
            const int half = w & 1;
            const uint32_t dst = sb + stage * STAGE_B + tile * TILE_B
                               + row * 48 + half * 16;
            const int row0 = (tile < 2) ? brow : bcol;
            cpa16(dst, srcs[tile] + (size_t)(row0 + row) * ND + kt * KSTEP + half * 8);
        }
        asm volatile("cp.async.commit_group;" ::: "memory");
    };

    load_stage(0, 0);

    const uint32_t a_row = lane & 15;
    const uint32_t a_coff = (lane >> 4) << 4;
    const uint32_t b_row = (lane & 7) + (((lane >> 4) & 1) << 3);
    const uint32_t b_coff = ((lane >> 3) & 1) << 4;

    for (int kt = 0; kt < NKT; kt++) {
        const int stage = kt & 1;
        if (kt + 1 < NKT) {
            load_stage(stage ^ 1, kt + 1);
            asm volatile("cp.async.wait_group 1;" ::: "memory");
        } else {
            asm volatile("cp.async.wait_group 0;" ::: "memory");
        }
        __syncthreads();

        const uint32_t base = sb + stage * STAGE_B;
        uint32_t ah[4][4], al[4][4], bh[2][4], bl[2][4];
#pragma unroll
        for (int mi = 0; mi < 4; mi++) {
            const uint32_t addr = base + (m0 + mi * 16 + a_row) * 48 + a_coff;
            ldsm4(ah[mi], addr);
            ldsm4(al[mi], addr + TILE_B);
        }
#pragma unroll
        for (int nj = 0; nj < 2; nj++) {
            const uint32_t addr = base + 2 * TILE_B
                                + (n0 + nj * 16 + b_row) * 48 + b_coff;
            ldsm4(bh[nj], addr);
            ldsm4(bl[nj], addr + TILE_B);
        }
#pragma unroll
        for (int mi = 0; mi < 4; mi++)
#pragma unroll
            for (int ni = 0; ni < 4; ni++) {
                const int j = ni >> 1, r = (ni & 1) * 2;
                mma16816(acc[mi][ni], ah[mi], bh[j][r], bh[j][r + 1]);
                mma16816(acc[mi][ni], ah[mi], bl[j][r], bl[j][r + 1]);
                mma16816(acc[mi][ni], al[mi], bh[j][r], bh[j][r + 1]);
            }
        __syncthreads();
    }

#pragma unroll
    for (int mi = 0; mi < 4; mi++) {
#pragma unroll
        for (int ni = 0; ni < 4; ni++) {
            const int mA = brow + m0 + mi * 16 + (lane >> 2);
            const int c = bcol + n0 + ni * 8 + ((lane & 3) << 1);
            float2 v0, v1;
            v0.x = acc[mi][ni][0]; v0.y = acc[mi][ni][1];
            v1.x = acc[mi][ni][2]; v1.y = acc[mi][ni][3];
            if (bias) {
                const float2 bv = *(const float2*)(bias + c);
                v0.x += bv.x; v0.y += bv.y;
                v1.x += bv.x; v1.y += bv.y;
            }
            if (MODE == 0) {
                *(float2*)&C[(size_t)mA * ND + c] = v0;
                *(float2*)&C[(size_t)(mA + 8) * ND + c] = v1;
            } else {
                const int hh = c >> 6, d = c & 63;
                const int b0_ = mA >> 10, t0 = mA & 1023;
                const int mB = mA + 8;
                const int b1_ = mB >> 10, t1 = mB & 1023;
                uint32_t h0, l0, h1, l1;
                split2(v0.x, v0.y, h0, l0);
                split2(v1.x, v1.y, h1, l1);
                if (MODE == 1) {
                    const size_t i0 = (((size_t)(b0_ * NH + hh) * NT + t0) << 6) + d;
                    const size_t i1 = (((size_t)(b1_ * NH + hh) * NT + t1) << 6) + d;
                    *(uint32_t*)&Ch[i0] = h0; *(uint32_t*)&Cl[i0] = l0;
                    *(uint32_t*)&Ch[i1] = h1; *(uint32_t*)&Cl[i1] = l1;
                } else {  // MODE 2: [b,h,d,t]
                    const size_t base0 = ((size_t)(b0_ * NH + hh) * HD + d) * NT + t0;
                    const size_t base1 = ((size_t)(b1_ * NH + hh) * HD + d) * NT + t1;
                    Ch[base0] = __ushort_as_bfloat16((unsigned short)(h0 & 0xFFFF));
                    Ch[base0 + NT] = __ushort_as_bfloat16((unsigned short)(h0 >> 16));
                    Cl[base0] = __ushort_as_bfloat16((unsigned short)(l0 & 0xFFFF));
                    Cl[base0 + NT] = __ushort_as_bfloat16((unsigned short)(l0 >> 16));
                    Ch[base1] = __ushort_as_bfloat16((unsigned short)(h1 & 0xFFFF));
                    Ch[base1 + NT] = __ushort_as_bfloat16((unsigned short)(h1 >> 16));
                    Cl[base1] = __ushort_as_bfloat16((unsigned short)(l1 & 0xFFFF));
                    Cl[base1 + NT] = __ushort_as_bfloat16((unsigned short)(l1 >> 16));
                }
            }
        }
    }
}

// ---------------- HMMA causal flash attention ------------------------------
// Block: 64 queries x one (b,h); 4 warps, each owns 16 query rows.
// K/V streamed in 64-key tiles; 3-pass split QK and PV; fp32 softmax.
// smem: 6 tiles (Qh,Ql,Kh,Kl,Vh,Vl) 64x64 bf16 = 8KB each, SW128-swizzled.
__global__ __launch_bounds__(128) void attn_hmma(
    const __nv_bfloat16* __restrict__ Qh, const __nv_bfloat16* __restrict__ Ql,
    const __nv_bfloat16* __restrict__ Kh, const __nv_bfloat16* __restrict__ Kl,
    const __nv_bfloat16* __restrict__ Vth, const __nv_bfloat16* __restrict__ Vtl,
    __nv_bfloat16* __restrict__ Oh, __nv_bfloat16* __restrict__ Ol)
{
    __shared__ __align__(1024) char sm[6 * 8192];
    const uint32_t sb = smem_to_u32(sm);
    const uint32_t sQh = sb, sQl = sb + 8192;
    const uint32_t sKh = sb + 16384, sKl = sb + 24576;
    const uint32_t sVh = sb + 32768, sVl = sb + 40960;

    const int qt = blockIdx.x;          // 64-query tile
    const int bh = blockIdx.y;
    const int tid = threadIdx.x;
    const int wid = tid >> 5;
    const int lane = tid & 31;

    const size_t qkoff = (size_t)bh * NT * HD;    // [b,h,t,d]
    const size_t voff = (size_t)bh * HD * NT;     // [b,h,d,t]

    // ---- load Q tile (h+l): 1024 16B chunks ----
#pragma unroll
    for (int i = 0; i < 8; i++) {
        const int c = i * 128 + tid;
        const int half = c >> 9;              // 0: Qh, 1: Ql
        const int w = c & 511;
        const int row = w >> 3;
        const int ch = w & 7;
        const uint32_t dst = (half ? sQl : sQh) + sw128(row * 128 + ch * 16);
        const __nv_bfloat16* src = (half ? Ql : Qh)
            + qkoff + (size_t)(qt * 64 + row) * HD + ch * 8;
        cpa16(dst, src);
    }
    asm volatile("cp.async.commit_group;" ::: "memory");
    asm volatile("cp.async.wait_group 0;" ::: "memory");
    __syncthreads();

    // ---- Q fragments (persist in regs) ----
    const uint32_t a_row = lane & 15;
    const uint32_t a_coff = (lane >> 4) << 4;
    const uint32_t b_row = (lane & 7) + (((lane >> 4) & 1) << 3);
    const uint32_t b_coff = ((lane >> 3) & 1) << 4;

    uint32_t qfh[4][4], qfl[4][4];
#pragma unroll
    for (int kc = 0; kc < 4; kc++) {
        const uint32_t off = sw128((wid * 16 + a_row) * 128 + kc * 32 + a_coff);
        ldsm4(qfh[kc], sQh + off);
        ldsm4(qfl[kc], sQl + off);
    }

    float O[8][4];
#pragma unroll
    for (int j = 0; j < 8; j++)
#pragma unroll
        for (int r = 0; r < 4; r++) O[j][r] = 0.0f;
    float mrow[2] = {-3.0e38f, -3.0e38f};
    float lrow[2] = {0.0f, 0.0f};

    const int rloc0 = wid * 16 + (lane >> 2);       // local query rows
    const int cloc = (lane & 3) << 1;

    for (int kt = 0; kt <= qt; kt++) {
        // ---- load K,V tiles (4 x 8KB): 2048 chunks ----
        __syncthreads();
#pragma unroll
        for (int i = 0; i < 16; i++) {
            const int c = i * 128 + tid;
            const int tile = c >> 9;          // 0:Kh 1:Kl 2:Vh 3:Vl
            const int w = c & 511;
            const int row = w >> 3;
            const int ch = w & 7;
            const uint32_t dsts[4] = {sKh, sKl, sVh, sVl};
            const uint32_t dst = dsts[tile] + sw128(row * 128 + ch * 16);
            const __nv_bfloat16* src;
            if (tile < 2)
                src = (tile ? Kl : Kh) + qkoff + (size_t)(kt * 64 + row) * HD + ch * 8;
            else
                src = (tile == 2 ? Vth : Vtl) + voff + (size_t)row * NT + kt * 64 + ch * 8;
            cpa16(dst, src);
        }
        asm volatile("cp.async.commit_group;" ::: "memory");
        asm volatile("cp.async.wait_group 0;" ::: "memory");
        __syncthreads();

        // ---- S = Q K^T (3-pass) ----
        float S[8][4];
#pragma unroll
        for (int j = 0; j < 8; j++)
#pragma unroll
            for (int r = 0; r < 4; r++) S[j][r] = 0.0f;

#pragma unroll
        for (int kc = 0; kc < 4; kc++) {
            uint32_t bKh[4][4], bKl[4][4];
#pragma unroll
            for (int nj = 0; nj < 4; nj++) {
                const uint32_t off = sw128((nj * 16 + b_row) * 128 + kc * 32 + b_coff);
                ldsm4(bKh[nj], sKh + off);
                ldsm4(bKl[nj], sKl + off);
            }
#pragma unroll
            for (int ni = 0; ni < 8; ni++) {
                const int j = ni >> 1, r = (ni & 1) * 2;
                mma16816(S[ni], qfh[kc], bKh[j][r], bKh[j][r + 1]);
                mma16816(S[ni], qfl[kc], bKh[j][r], bKh[j][r + 1]);
                mma16816(S[ni], qfh[kc], bKl[j][r], bKl[j][r + 1]);
            }
        }

        // ---- scale + causal mask (diagonal tile only) ----
#pragma unroll
        for (int j = 0; j < 8; j++)
#pragma unroll
            for (int r = 0; r < 4; r++) S[j][r] *= 0.125f;
        if (kt == qt) {
#pragma unroll
            for (int j = 0; j < 8; j++)
#pragma unroll
                for (int r = 0; r < 4; r++) {
                    const int rq = rloc0 + (r >> 1) * 8;
                    const int ck = j * 8 + cloc + (r & 1);
                    if (ck > rq) S[j][r] = -1.0e30f;
                }
        }

        // ---- online softmax ----
#pragma unroll
        for (int g = 0; g < 2; g++) {
            float mx = -3.0e38f;
#pragma unroll
            for (int j = 0; j < 8; j++) {
                mx = fmaxf(mx, S[j][g * 2]);
                mx = fmaxf(mx, S[j][g * 2 + 1]);
            }
            mx = fmaxf(mx, __shfl_xor_sync(0xffffffffu, mx, 1));
            mx = fmaxf(mx, __shfl_xor_sync(0xffffffffu, mx, 2));
            const float mnew = fmaxf(mrow[g], mx);
            const float corr = __expf(mrow[g] - mnew);
            mrow[g] = mnew;
            float ps = 0.0f;
#pragma unroll
            for (int j = 0; j < 8; j++) {
                S[j][g * 2] = __expf(S[j][g * 2] - mnew);
                S[j][g * 2 + 1] = __expf(S[j][g * 2 + 1] - mnew);
                ps += S[j][g * 2] + S[j][g * 2 + 1];
            }
            ps += __shfl_xor_sync(0xffffffffu, ps, 1);
            ps += __shfl_xor_sync(0xffffffffu, ps, 2);
            lrow[g] = lrow[g] * corr + ps;
#pragma unroll
            for (int j = 0; j < 8; j++) {
                O[j][g * 2] *= corr;
                O[j][g * 2 + 1] *= corr;
            }
        }

        // ---- O += P V (3-pass) ----
#pragma unroll
        for (int kc = 0; kc < 4; kc++) {
            uint32_t aPh[4], aPl[4];
            split2(S[2 * kc][0], S[2 * kc][1], aPh[0], aPl[0]);
            split2(S[2 * kc][2], S[2 * kc][3], aPh[1], aPl[1]);
            split2(S[2 * kc + 1][0], S[2 * kc + 1][1], aPh[2], aPl[2]);
            split2(S[2 * kc + 1][2], S[2 * kc + 1][3], aPh[3], aPl[3]);
            uint32_t bVh[4][4], bVl[4][4];
#pragma unroll
            for (int nj = 0; nj < 4; nj++) {
                const uint32_t off = sw128((nj * 16 + b_row) * 128 + kc * 32 + b_coff);
                ldsm4(bVh[nj], sVh + off);
                ldsm4(bVl[nj], sVl + off);
            }
#pragma unroll
            for (int ni = 0; ni < 8; ni++) {
                const int j = ni >> 1, r = (ni & 1) * 2;
                mma16816(O[ni], aPh, bVh[j][r], bVh[j][r + 1]);
                mma16816(O[ni], aPl, bVh[j][r], bVh[j][r + 1]);
                mma16816(O[ni], aPh, bVl[j][r], bVl[j][r + 1]);
            }
        }
    }

    // ---- epilogue: normalize, split, write [b,t,D] ----
    const float inv0 = 1.0f / lrow[0];
    const float inv1 = 1.0f / lrow[1];
    const int b = bh >> 4, hh = bh & 15;
    const int tq0 = qt * 64 + rloc0;
#pragma unroll
    for (int j = 0; j < 8; j++) {
        const int d = hh * 64 + j * 8 + cloc;
        uint32_t h0, l0, h1, l1;
        split2(O[j][0] * inv0, O[j][1] * inv0, h0, l0);
        split2(O[j][2] * inv1, O[j][3] * inv1, h1, l1);
        const size_t i0 = ((size_t)b * NT + tq0) * ND + d;
        const size_t i1 = ((size_t)b * NT + tq0 + 8) * ND + d;
        *(uint32_t*)&Oh[i0] = h0; *(uint32_t*)&Ol[i0] = l0;
        *(uint32_t*)&Oh[i1] = h1; *(uint32_t*)&Ol[i1] = l1;
    }
}

// ---------------------------------------------------------------------------
// Inputs (metadata order): x, mask, Wq, bq, Wk, Wv, bv, Wo, bo
// ---------------------------------------------------------------------------
extern "C" void kernel_launch(void* const* d_in, const int* in_sizes, int n_in,
                              void* d_out, int out_size)
{
    const float* x  = (const float*)d_in[0];
    const float* Wq = (const float*)d_in[2];
    const float* bq = (const float*)d_in[3];
    const float* Wk = (const float*)d_in[4];
    const float* Wv = (const float*)d_in[5];
    const float* bv = (const float*)d_in[6];
    const float* Wo = (const float*)d_in[7];
    const float* bo = (const float*)d_in[8];
    float* out = (float*)d_out;

    __nv_bfloat16 *xh, *xl, *qh, *ql, *kh, *kl, *vth, *vtl, *aoh, *aol;
    __nv_bfloat16 *wqh, *wql, *wkh, *wkl, *wvh, *wvl, *woh, *wol;
    cudaGetSymbolAddress((void**)&xh, g_xh);   cudaGetSymbolAddress((void**)&xl, g_xl);
    cudaGetSymbolAddress((void**)&qh, g_qh);   cudaGetSymbolAddress((void**)&ql, g_ql);
    cudaGetSymbolAddress((void**)&kh, g_kh);   cudaGetSymbolAddress((void**)&kl, g_kl);
    cudaGetSymbolAddress((void**)&vth, g_vth); cudaGetSymbolAddress((void**)&vtl, g_vtl);
    cudaGetSymbolAddress((void**)&aoh, g_aoh); cudaGetSymbolAddress((void**)&aol, g_aol);
    cudaGetSymbolAddress((void**)&wqh, g_wqh); cudaGetSymbolAddress((void**)&wql, g_wql);
    cudaGetSymbolAddress((void**)&wkh, g_wkh); cudaGetSymbolAddress((void**)&wkl, g_wkl);
    cudaGetSymbolAddress((void**)&wvh, g_wvh); cudaGetSymbolAddress((void**)&wvl, g_wvl);
    cudaGetSymbolAddress((void**)&woh, g_woh); cudaGetSymbolAddress((void**)&wol, g_wol);

    const int M = NB * NT;
    const int xn4 = M * ND / 4;
    const int wn4 = ND * ND / 4;

    split_kernel<<<(xn4 + 255) / 256, 256>>>(x, xh, xl, xn4);
    split_kernel<<<(wn4 + 255) / 256, 256>>>(Wq, wqh, wql, wn4);
    split_kernel<<<(wn4 + 255) / 256, 256>>>(Wk, wkh, wkl, wn4);
    split_kernel<<<(wn4 + 255) / 256, 256>>>(Wv, wvh, wvl, wn4);
    split_kernel<<<(wn4 + 255) / 256, 256>>>(Wo, woh, wol, wn4);

    dim3 gemm_grid(ND / 128, M / 128);
    gemm_hmma<1><<<gemm_grid, 256, GEMM_SMEM>>>(xh, xl, wqh, wql, bq, nullptr, qh, ql);
    gemm_hmma<1><<<gemm_grid, 256, GEMM_SMEM>>>(xh, xl, wkh, wkl, nullptr, nullptr, kh, kl);
    gemm_hmma<2><<<gemm_grid, 256, GEMM_SMEM>>>(xh, xl, wvh, wvl, bv, nullptr, vth, vtl);

    attn_hmma<<<dim3(NT / 64, NB * NH), 128>>>(qh, ql, kh, kl, vth, vtl, aoh, aol);

    gemm_hmma<0><<<gemm_grid, 256, GEMM_SMEM>>>(aoh, aol, woh, wol, bo, out, nullptr, nullptr);
}

// round 7
// speedup vs baseline: 5.0503x; 1.3119x over previous
#include <cuda_runtime.h>
#include <cstdint>

#define NB 8
#define NT 1024
#define ND 1024
#define NH 16
#define HD 64
// hd^-0.5 * log2(e), folded into Q projection output (exp2-domain softmax)
#define QSCALE 0.1803368801111243f

// ---------------- scratch (device globals; no allocation allowed) ----------
__device__ float g_xr[NB * NT * ND];
__device__ float g_wqr[ND * ND], g_wkr[ND * ND], g_wvr[ND * ND], g_wor[ND * ND];
__device__ float g_q[NB * NH * NT * HD], g_k[NB * NH * NT * HD], g_v[NB * NH * NT * HD];
__device__ float g_ao[NB * NT * ND];

// ---------------- helpers ---------------------------------------------------
__device__ __forceinline__ uint32_t smem_to_u32(const void* p) {
    uint32_t a;
    asm("{ .reg .u64 t; cvta.to.shared.u64 t, %1; cvt.u32.u64 %0, t; }"
        : "=r"(a) : "l"(p));
    return a;
}
__device__ __forceinline__ uint32_t lds32(uint32_t a) {
    uint32_t v;
    asm volatile("ld.shared.b32 %0, [%1];" : "=r"(v) : "r"(a));
    return v;
}
__device__ __forceinline__ void cpa16(uint32_t dst, const void* gsrc) {
    asm volatile("cp.async.cg.shared.global [%0], [%1], 16;"
                 :: "r"(dst), "l"(__cvta_generic_to_global(gsrc)) : "memory");
}
__device__ __forceinline__ uint32_t f2tf(float f) {
    uint32_t r;
    asm("cvt.rna.tf32.f32 %0, %1;" : "=r"(r) : "f"(f));
    return r;
}
__device__ __forceinline__ float ex2(float x) {
    float r;
    asm("ex2.approx.f32 %0, %1;" : "=f"(r) : "f"(x));
    return r;
}
// D += A(16x8) * B(8x8); A,B tf32 bit patterns in b32 regs.
__device__ __forceinline__ void mma_tf32(float* d, const uint32_t* a,
                                         uint32_t b0, uint32_t b1) {
    asm volatile(
        "mma.sync.aligned.m16n8k8.row.col.f32.tf32.tf32.f32 "
        "{%0,%1,%2,%3}, {%4,%5,%6,%7}, {%8,%9}, {%0,%1,%2,%3};"
        : "+f"(d[0]), "+f"(d[1]), "+f"(d[2]), "+f"(d[3])
        : "r"(a[0]), "r"(a[1]), "r"(a[2]), "r"(a[3]), "r"(b0), "r"(b1));
}

// ---------------- tf32 pre-rounding kernel ----------------------------------
__global__ __launch_bounds__(256) void tf32_round_kernel(
    const float* __restrict__ src, float* __restrict__ dst, int n4)
{
    int i = blockIdx.x * 256 + threadIdx.x;
    if (i >= n4) return;
    float4 v = ((const float4*)src)[i];
    uint4 o;
    o.x = f2tf(v.x); o.y = f2tf(v.y); o.z = f2tf(v.z); o.w = f2tf(v.w);
    ((uint4*)dst)[i] = o;
}

// ---------------- tf32 single-pass GEMM -------------------------------------
// C[m,n] = (sum_k A[m,k]*W[n,k] + bias[n]) * scale
// A [M,1024], W [1024,1024], both tf32-pre-rounded fp32, K-major.
// CTA 128x128, 8 warps (2m x 4n), warp 64x32, k-step 16, double-buffered.
// smem rows padded to 20 words (80B): 8-row x 4-col fragment reads hit 32
// distinct banks (20*r mod 32 covers multiples of 4).
// MODE 0: fp32 out [M,1024].  MODE 1: tf32-rounded fp32, head-major [b,h,t,d].
template <int MODE>
__global__ __launch_bounds__(256, 1) void gemm_tf32(
    const float* __restrict__ A, const float* __restrict__ B,
    const float* __restrict__ bias, float scale, float* __restrict__ C)
{
    __shared__ __align__(16) float smf[10240];     // 2 stages x (A+B) = 40KB
    const uint32_t sb = smem_to_u32(smf);
    const int tid = threadIdx.x;
    const int wid = tid >> 5;
    const int lane = tid & 31;
    const int m0 = (wid >> 2) * 64;
    const int n0 = (wid & 3) * 32;
    const int brow = blockIdx.y * 128;
    const int bcol = blockIdx.x * 128;

    float acc[4][4][4];
#pragma unroll
    for (int i = 0; i < 4; i++)
#pragma unroll
        for (int j = 0; j < 4; j++)
#pragma unroll
            for (int r = 0; r < 4; r++) acc[i][j][r] = 0.0f;

    auto load_stage = [&](int s, int kt) {
#pragma unroll
        for (int i = 0; i < 4; i++) {
            const int c = i * 256 + tid;          // 1024 chunks of 16B
            const int tile = c >> 9;              // 0:A 1:B
            const int w = c & 511;
            const int row = w >> 2;
            const int ch = w & 3;
            const uint32_t dst = sb + s * 20480 + tile * 10240 + row * 80 + ch * 16;
            const float* src = (tile ? B + (size_t)(bcol + row) * ND
                                     : A + (size_t)(brow + row) * ND)
                               + kt * 16 + ch * 4;
            cpa16(dst, src);
        }
        asm volatile("cp.async.commit_group;" ::: "memory");
    };

    load_stage(0, 0);

    for (int kt = 0; kt < 64; kt++) {
        const int s = kt & 1;
        if (kt + 1 < 64) {
            load_stage(s ^ 1, kt + 1);
            asm volatile("cp.async.wait_group 1;" ::: "memory");
        } else {
            asm volatile("cp.async.wait_group 0;" ::: "memory");
        }
        __syncthreads();

        const uint32_t base = sb + s * 20480;
#pragma unroll
        for (int kc = 0; kc < 2; kc++) {
            uint32_t a[4][4], b[4][2];
#pragma unroll
            for (int mi = 0; mi < 4; mi++) {
                const uint32_t w0 = base + (uint32_t)(m0 + 16 * mi + (lane >> 2)) * 80
                                  + kc * 32 + (lane & 3) * 4;
                a[mi][0] = lds32(w0);        // (r,   c)
                a[mi][1] = lds32(w0 + 640);  // (r+8, c)
                a[mi][2] = lds32(w0 + 16);   // (r,   c+4)
                a[mi][3] = lds32(w0 + 656);  // (r+8, c+4)
            }
#pragma unroll
            for (int nj = 0; nj < 4; nj++) {
                const uint32_t w0 = base + 10240
                                  + (uint32_t)(n0 + 8 * nj + (lane >> 2)) * 80
                                  + kc * 32 + (lane & 3) * 4;
                b[nj][0] = lds32(w0);        // (k,   n)
                b[nj][1] = lds32(w0 + 16);   // (k+4, n)
            }
#pragma unroll
            for (int mi = 0; mi < 4; mi++)
#pragma unroll
                for (int nj = 0; nj < 4; nj++)
                    mma_tf32(acc[mi][nj], a[mi], b[nj][0], b[nj][1]);
        }
        __syncthreads();
    }

#pragma unroll
    for (int mi = 0; mi < 4; mi++) {
#pragma unroll
        for (int nj = 0; nj < 4; nj++) {
            const int mA = brow + m0 + 16 * mi + (lane >> 2);
            const int c = bcol + n0 + 8 * nj + ((lane & 3) << 1);
            float2 v0, v1;
            v0.x = acc[mi][nj][0]; v0.y = acc[mi][nj][1];
            v1.x = acc[mi][nj][2]; v1.y = acc[mi][nj][3];
            if (bias) {
                const float2 bv = *(const float2*)(bias + c);
                v0.x += bv.x; v0.y += bv.y;
                v1.x += bv.x; v1.y += bv.y;
            }
            v0.x *= scale; v0.y *= scale; v1.x *= scale; v1.y *= scale;
            if (MODE == 0) {
                *(float2*)&C[(size_t)mA * ND + c] = v0;
                *(float2*)&C[(size_t)(mA + 8) * ND + c] = v1;
            } else {
                const int hh = c >> 6, d = c & 63;
                const int b0_ = mA >> 10, t0 = mA & 1023;
                const int mB = mA + 8;
                const int b1_ = mB >> 10, t1 = mB & 1023;
                const size_t i0 = (((size_t)(b0_ * NH + hh) * NT + t0) << 6) + d;
                const size_t i1 = (((size_t)(b1_ * NH + hh) * NT + t1) << 6) + d;
                uint2 u0, u1;
                u0.x = f2tf(v0.x); u0.y = f2tf(v0.y);
                u1.x = f2tf(v1.x); u1.y = f2tf(v1.y);
                *(uint2*)&C[i0] = u0;
                *(uint2*)&C[i1] = u1;
            }
        }
    }
}

// ---------------- tf32 causal flash attention -------------------------------
// Block: 128 queries x one (b,h); 8 warps, each 16 query rows. K/V streamed
// in 64-key tiles, double-buffered via cp.async. Q,K,V are tf32-pre-rounded
// fp32 in [b,h,t,d]. Scores already in exp2 domain (QSCALE folded).
// smem (bytes): Q[0,34816) K0[34816) V0[52224) K1[70656) V1[88064); 106496 total.
// Q/K row stride 272B (68w), V row stride 288B (72w) — conflict-free frags.
__global__ __launch_bounds__(256) void attn_tf32(
    const float* __restrict__ Q, const float* __restrict__ K,
    const float* __restrict__ V, float* __restrict__ Ao)
{
    extern __shared__ __align__(16) float smf[];
    const uint32_t sb = smem_to_u32(smf);
    const int qt = gridDim.x - 1 - blockIdx.x;   // heavy blocks first
    const int bh = blockIdx.y;
    const int tid = threadIdx.x;
    const int wid = tid >> 5;
    const int lane = tid & 31;

    const size_t off = (size_t)bh * NT * HD;
    const float* Qg = Q + off;
    const float* Kg = K + off;
    const float* Vg = V + off;

    auto load_tile = [&](int kt, int s) {
        const uint32_t kb = sb + 34816 + s * 35840;
        const uint32_t vb = kb + 17408;
#pragma unroll
        for (int i = 0; i < 8; i++) {
            const int c = i * 256 + tid;      // 2048 chunks
            const int tile = c >> 10;         // 0:K 1:V
            const int w = c & 1023;
            const int row = w >> 4;
            const int ch = w & 15;
            if (tile == 0)
                cpa16(kb + row * 272 + ch * 16,
                      Kg + (size_t)(kt * 64 + row) * HD + ch * 4);
            else
                cpa16(vb + row * 288 + ch * 16,
                      Vg + (size_t)(kt * 64 + row) * HD + ch * 4);
        }
        asm volatile("cp.async.commit_group;" ::: "memory");
    };

    // ---- load Q (128 x 64): 2048 chunks ----
#pragma unroll
    for (int i = 0; i < 8; i++) {
        const int c = i * 256 + tid;
        const int row = c >> 4;
        const int ch = c & 15;
        cpa16(sb + row * 272 + ch * 16,
              Qg + (size_t)(qt * 128 + row) * HD + ch * 4);
    }
    asm volatile("cp.async.commit_group;" ::: "memory");

    const int nkt = 2 * qt + 2;
    load_tile(0, 0);
    asm volatile("cp.async.wait_group 1;" ::: "memory");   // Q done
    __syncthreads();

    float O[8][4];
#pragma unroll
    for (int j = 0; j < 8; j++)
#pragma unroll
        for (int r = 0; r < 4; r++) O[j][r] = 0.0f;
    float mrow[2] = {-3.0e38f, -3.0e38f};
    float lrow[2] = {0.0f, 0.0f};

    const int rloc0 = 16 * wid + (lane >> 2);
    const int cloc = (lane & 3) << 1;
    const uint32_t qrowb = sb + (uint32_t)rloc0 * 272 + (lane & 3) * 4;

    for (int kt = 0; kt < nkt; kt++) {
        const int s = kt & 1;
        if (kt + 1 < nkt) {
            load_tile(kt + 1, s ^ 1);
            asm volatile("cp.async.wait_group 1;" ::: "memory");
        } else {
            asm volatile("cp.async.wait_group 0;" ::: "memory");
        }
        __syncthreads();

        const uint32_t kb = sb + 34816 + s * 35840;
        const uint32_t vb = kb + 17408;

        // ---- S = Q K^T (tf32 single pass) ----
        float S[8][4];
#pragma unroll
        for (int j = 0; j < 8; j++)
#pragma unroll
            for (int r = 0; r < 4; r++) S[j][r] = 0.0f;

#pragma unroll
        for (int kc = 0; kc < 8; kc++) {
            uint32_t qf[4];
            const uint32_t qw = qrowb + kc * 32;
            qf[0] = lds32(qw);        // (r,   c)
            qf[1] = lds32(qw + 2176); // (r+8, c)
            qf[2] = lds32(qw + 16);   // (r,   c+4)
            qf[3] = lds32(qw + 2192); // (r+8, c+4)
#pragma unroll
            for (int nj = 0; nj < 8; nj++) {
                const uint32_t w0 = kb + (uint32_t)(8 * nj + (lane >> 2)) * 272
                                  + kc * 32 + (lane & 3) * 4;
                mma_tf32(S[nj], qf, lds32(w0), lds32(w0 + 16));
            }
        }

        // ---- causal mask (only last two tiles can intersect diagonal) ----
        if (kt >= 2 * qt) {
#pragma unroll
            for (int j = 0; j < 8; j++)
#pragma unroll
                for (int r = 0; r < 4; r++) {
                    const int rq = qt * 128 + rloc0 + (r >> 1) * 8;
                    const int ck = kt * 64 + j * 8 + cloc + (r & 1);
                    if (ck > rq) S[j][r] = -1.0e30f;
                }
        }

        // ---- online softmax (exp2 domain) ----
#pragma unroll
        for (int g = 0; g < 2; g++) {
            float mx = -3.0e38f;
#pragma unroll
            for (int j = 0; j < 8; j++) {
                mx = fmaxf(mx, S[j][g * 2]);
                mx = fmaxf(mx, S[j][g * 2 + 1]);
            }
            mx = fmaxf(mx, __shfl_xor_sync(0xffffffffu, mx, 1));
            mx = fmaxf(mx, __shfl_xor_sync(0xffffffffu, mx, 2));
            const float mnew = fmaxf(mrow[g], mx);
            const float corr = ex2(mrow[g] - mnew);
            mrow[g] = mnew;
            float ps = 0.0f;
#pragma unroll
            for (int j = 0; j < 8; j++) {
                S[j][g * 2] = ex2(S[j][g * 2] - mnew);
                S[j][g * 2 + 1] = ex2(S[j][g * 2 + 1] - mnew);
                ps += S[j][g * 2] + S[j][g * 2 + 1];
            }
            ps += __shfl_xor_sync(0xffffffffu, ps, 1);
            ps += __shfl_xor_sync(0xffffffffu, ps, 2);
            lrow[g] = lrow[g] * corr + ps;
#pragma unroll
            for (int j = 0; j < 8; j++) {
                O[j][g * 2] *= corr;
                O[j][g * 2 + 1] *= corr;
            }
        }

        // ---- O += P V: relayout C-frag -> A-frag via shuffles, then mma ----
        const int srcA = (lane & 28) | ((lane & 3) >> 1);
        const int srcB = srcA + 2;
        const bool odd = lane & 1;
#pragma unroll
        for (int kc = 0; kc < 8; kc++) {
            const float v00 = __shfl_sync(0xffffffffu, S[kc][0], srcA);
            const float v01 = __shfl_sync(0xffffffffu, S[kc][1], srcA);
            const float v10 = __shfl_sync(0xffffffffu, S[kc][2], srcA);
            const float v11 = __shfl_sync(0xffffffffu, S[kc][3], srcA);
            const float v20 = __shfl_sync(0xffffffffu, S[kc][0], srcB);
            const float v21 = __shfl_sync(0xffffffffu, S[kc][1], srcB);
            const float v30 = __shfl_sync(0xffffffffu, S[kc][2], srcB);
            const float v31 = __shfl_sync(0xffffffffu, S[kc][3], srcB);
            uint32_t a[4];
            a[0] = f2tf(odd ? v01 : v00);  // (r,   k)
            a[1] = f2tf(odd ? v11 : v10);  // (r+8, k)
            a[2] = f2tf(odd ? v21 : v20);  // (r,   k+4)
            a[3] = f2tf(odd ? v31 : v30);  // (r+8, k+4)
#pragma unroll
            for (int nj = 0; nj < 8; nj++) {
                const uint32_t w0 = vb + (uint32_t)(8 * kc + (lane & 3)) * 288
                                  + (uint32_t)(8 * nj + (lane >> 2)) * 4;
                mma_tf32(O[nj], a, lds32(w0), lds32(w0 + 1152));
            }
        }
        __syncthreads();   // stage s free for the load issued next iteration
    }

    // ---- epilogue: normalize, tf32-round, write [b,t,D] ----
    const float inv0 = 1.0f / lrow[0];
    const float inv1 = 1.0f / lrow[1];
    const int b = bh >> 4, hh = bh & 15;
    const int tq0 = qt * 128 + rloc0;
#pragma unroll
    for (int nj = 0; nj < 8; nj++) {
        const int d = hh * 64 + nj * 8 + cloc;
        uint2 u0, u1;
        u0.x = f2tf(O[nj][0] * inv0); u0.y = f2tf(O[nj][1] * inv0);
        u1.x = f2tf(O[nj][2] * inv1); u1.y = f2tf(O[nj][3] * inv1);
        *(uint2*)&Ao[((size_t)b * NT + tq0) * ND + d] = u0;
        *(uint2*)&Ao[((size_t)b * NT + tq0 + 8) * ND + d] = u1;
    }
}

// ---------------------------------------------------------------------------
// Inputs (metadata order): x, mask, Wq, bq, Wk, Wv, bv, Wo, bo
// ---------------------------------------------------------------------------
extern "C" void kernel_launch(void* const* d_in, const int* in_sizes, int n_in,
                              void* d_out, int out_size)
{
    const float* x  = (const float*)d_in[0];
    const float* Wq = (const float*)d_in[2];
    const float* bq = (const float*)d_in[3];
    const float* Wk = (const float*)d_in[4];
    const float* Wv = (const float*)d_in[5];
    const float* bv = (const float*)d_in[6];
    const float* Wo = (const float*)d_in[7];
    const float* bo = (const float*)d_in[8];
    float* out = (float*)d_out;

    float *xr, *wqr, *wkr, *wvr, *wor, *qp, *kp, *vp, *aop;
    cudaGetSymbolAddress((void**)&xr, g_xr);
    cudaGetSymbolAddress((void**)&wqr, g_wqr);
    cudaGetSymbolAddress((void**)&wkr, g_wkr);
    cudaGetSymbolAddress((void**)&wvr, g_wvr);
    cudaGetSymbolAddress((void**)&wor, g_wor);
    cudaGetSymbolAddress((void**)&qp, g_q);
    cudaGetSymbolAddress((void**)&kp, g_k);
    cudaGetSymbolAddress((void**)&vp, g_v);
    cudaGetSymbolAddress((void**)&aop, g_ao);

    cudaFuncSetAttribute(attn_tf32,
                         cudaFuncAttributeMaxDynamicSharedMemorySize, 106496);

    const int M = NB * NT;                 // 8192
    const int xn4 = M * ND / 4;            // 2M
    const int wn4 = ND * ND / 4;           // 256K

    tf32_round_kernel<<<(xn4 + 255) / 256, 256>>>(x, xr, xn4);
    tf32_round_kernel<<<(wn4 + 255) / 256, 256>>>(Wq, wqr, wn4);
    tf32_round_kernel<<<(wn4 + 255) / 256, 256>>>(Wk, wkr, wn4);
    tf32_round_kernel<<<(wn4 + 255) / 256, 256>>>(Wv, wvr, wn4);
    tf32_round_kernel<<<(wn4 + 255) / 256, 256>>>(Wo, wor, wn4);

    dim3 gemm_grid(ND / 128, M / 128);     // (8, 64)
    gemm_tf32<1><<<gemm_grid, 256>>>(xr, wqr, bq, QSCALE, qp);
    gemm_tf32<1><<<gemm_grid, 256>>>(xr, wkr, nullptr, 1.0f, kp);
    gemm_tf32<1><<<gemm_grid, 256>>>(xr, wvr, bv, 1.0f, vp);

    attn_tf32<<<dim3(NT / 128, NB * NH), 256, 106496>>>(qp, kp, vp, aop);

    gemm_tf32<0><<<gemm_grid, 256>>>(aop, wor, bo, 1.0f, out);
}

// round 11
// speedup vs baseline: 5.8580x; 1.1599x over previous
#include <cuda_runtime.h>
#include <cstdint>

#define NB 8
#define NT 1024
#define ND 1024
#define NH 16
#define HD 64
// hd^-0.5 * log2(e), folded into Q projection output (exp2-domain softmax)
#define QSCALE 0.1803368801111243f

// ---------------- scratch (device globals; no allocation allowed) ----------
__device__ float g_xr[NB * NT * ND];
__device__ float g_wqr[ND * ND], g_wkr[ND * ND], g_wvr[ND * ND], g_wor[ND * ND];
__device__ float g_q[NB * NH * NT * HD], g_k[NB * NH * NT * HD], g_v[NB * NH * NT * HD];
__device__ float g_ao[NB * NT * ND];

// ---------------- helpers ---------------------------------------------------
__device__ __forceinline__ uint32_t smem_to_u32(const void* p) {
    uint32_t a;
    asm("{ .reg .u64 t; cvta.to.shared.u64 t, %1; cvt.u32.u64 %0, t; }"
        : "=r"(a) : "l"(p));
    return a;
}
__device__ __forceinline__ uint32_t lds32(uint32_t a) {
    uint32_t v;
    asm volatile("ld.shared.b32 %0, [%1];" : "=r"(v) : "r"(a));
    return v;
}
__device__ __forceinline__ void cpa16(uint32_t dst, const void* gsrc) {
    asm volatile("cp.async.cg.shared.global [%0], [%1], 16;"
                 :: "r"(dst), "l"(__cvta_generic_to_global(gsrc)) : "memory");
}
__device__ __forceinline__ uint32_t f2tf(float f) {
    uint32_t r;
    asm("cvt.rna.tf32.f32 %0, %1;" : "=r"(r) : "f"(f));
    return r;
}
__device__ __forceinline__ float ex2(float x) {
    float r;
    asm("ex2.approx.f32 %0, %1;" : "=f"(r) : "f"(x));
    return r;
}
__device__ __forceinline__ void mma_tf32(float* d, const uint32_t* a,
                                         uint32_t b0, uint32_t b1) {
    asm volatile(
        "mma.sync.aligned.m16n8k8.row.col.f32.tf32.tf32.f32 "
        "{%0,%1,%2,%3}, {%4,%5,%6,%7}, {%8,%9}, {%0,%1,%2,%3};"
        : "+f"(d[0]), "+f"(d[1]), "+f"(d[2]), "+f"(d[3])
        : "r"(a[0]), "r"(a[1]), "r"(a[2]), "r"(a[3]), "r"(b0), "r"(b1));
}

// ---------------- tf32 pre-rounding kernel ----------------------------------
__global__ __launch_bounds__(256) void tf32_round_kernel(
    const float* __restrict__ src, float* __restrict__ dst, int n4)
{
    int i = blockIdx.x * 256 + threadIdx.x;
    if (i >= n4) return;
    float4 v = ((const float4*)src)[i];
    uint4 o;
    o.x = f2tf(v.x); o.y = f2tf(v.y); o.z = f2tf(v.z); o.w = f2tf(v.w);
    ((uint4*)dst)[i] = o;
}

// ---------------- tf32 GEMM: CTA 256x128, warp 64x64 ------------------------
// C[m,n] = (sum_k A[m,k]*W[n,k] + bias[n]) * scale ; A [M,1024], W [1024,1024]
// 8 warps as 4m x 2n. k-step 16, double-buffered cp.async.
// smem/stage: A 256 rows x 80B = 20480, B 128 x 80 = 10240 -> 30720; x2 = 61440.
// MODE 0: fp32 out [M,1024].  MODE 1: tf32-rounded fp32, head-major [b,h,t,d].
template <int MODE>
__global__ __launch_bounds__(256, 1) void gemm_tf32(
    const float* __restrict__ A, const float* __restrict__ B,
    const float* __restrict__ bias, float scale, float* __restrict__ C)
{
    extern __shared__ __align__(16) float smf[];
    const uint32_t sb = smem_to_u32(smf);
    const int tid = threadIdx.x;
    const int wid = tid >> 5;
    const int lane = tid & 31;
    const int g = lane >> 2;
    const int t = lane & 3;
    const int m0 = (wid >> 1) * 64;        // 4 m-groups of 64
    const int n0 = (wid & 1) * 64;         // 2 n-groups of 64
    const int brow = blockIdx.y * 256;
    const int bcol = blockIdx.x * 128;

    float acc[4][8][4];
#pragma unroll
    for (int i = 0; i < 4; i++)
#pragma unroll
        for (int j = 0; j < 8; j++)
#pragma unroll
            for (int r = 0; r < 4; r++) acc[i][j][r] = 0.0f;

    auto load_stage = [&](int s, int kt) {
#pragma unroll
        for (int i = 0; i < 6; i++) {
            const int c = i * 256 + tid;          // 1536 chunks of 16B
            uint32_t dst;
            const float* src;
            if (c < 1024) {                       // A: 256 rows x 4 chunks
                const int row = c >> 2, ch = c & 3;
                dst = sb + s * 30720 + row * 80 + ch * 16;
                src = A + (size_t)(brow + row) * ND + kt * 16 + ch * 4;
            } else {                              // B: 128 rows x 4 chunks
                const int w = c - 1024;
                const int row = w >> 2, ch = w & 3;
                dst = sb + s * 30720 + 20480 + row * 80 + ch * 16;
                src = B + (size_t)(bcol + row) * ND + kt * 16 + ch * 4;
            }
            cpa16(dst, src);
        }
        asm volatile("cp.async.commit_group;" ::: "memory");
    };

    load_stage(0, 0);

    for (int kt = 0; kt < 64; kt++) {
        const int s = kt & 1;
        if (kt + 1 < 64) {
            load_stage(s ^ 1, kt + 1);
            asm volatile("cp.async.wait_group 1;" ::: "memory");
        } else {
            asm volatile("cp.async.wait_group 0;" ::: "memory");
        }
        __syncthreads();

        const uint32_t base = sb + s * 30720;
#pragma unroll
        for (int kc = 0; kc < 2; kc++) {
            uint32_t a[4][4], b[8][2];
#pragma unroll
            for (int mi = 0; mi < 4; mi++) {
                const uint32_t w0 = base + (uint32_t)(m0 + 16 * mi + g) * 80
                                  + kc * 32 + t * 4;
                a[mi][0] = lds32(w0);
                a[mi][1] = lds32(w0 + 640);
                a[mi][2] = lds32(w0 + 16);
                a[mi][3] = lds32(w0 + 656);
            }
#pragma unroll
            for (int nj = 0; nj < 8; nj++) {
                const uint32_t w0 = base + 20480
                                  + (uint32_t)(n0 + 8 * nj + g) * 80
                                  + kc * 32 + t * 4;
                b[nj][0] = lds32(w0);
                b[nj][1] = lds32(w0 + 16);
            }
#pragma unroll
            for (int mi = 0; mi < 4; mi++)
#pragma unroll
                for (int nj = 0; nj < 8; nj++)
                    mma_tf32(acc[mi][nj], a[mi], b[nj][0], b[nj][1]);
        }
        __syncthreads();
    }

#pragma unroll
    for (int mi = 0; mi < 4; mi++) {
#pragma unroll
        for (int nj = 0; nj < 8; nj++) {
            const int mA = brow + m0 + 16 * mi + g;
            const int c = bcol + n0 + 8 * nj + 2 * t;
            float2 v0, v1;
            v0.x = acc[mi][nj][0]; v0.y = acc[mi][nj][1];
            v1.x = acc[mi][nj][2]; v1.y = acc[mi][nj][3];
            if (bias) {
                const float2 bv = *(const float2*)(bias + c);
                v0.x += bv.x; v0.y += bv.y;
                v1.x += bv.x; v1.y += bv.y;
            }
            v0.x *= scale; v0.y *= scale; v1.x *= scale; v1.y *= scale;
            if (MODE == 0) {
                *(float2*)&C[(size_t)mA * ND + c] = v0;
                *(float2*)&C[(size_t)(mA + 8) * ND + c] = v1;
            } else {
                const int hh = c >> 6, d = c & 63;
                const int b0_ = mA >> 10, t0 = mA & 1023;
                const int mB = mA + 8;
                const int b1_ = mB >> 10, t1 = mB & 1023;
                const size_t i0 = (((size_t)(b0_ * NH + hh) * NT + t0) << 6) + d;
                const size_t i1 = (((size_t)(b1_ * NH + hh) * NT + t1) << 6) + d;
                uint2 u0, u1;
                u0.x = f2tf(v0.x); u0.y = f2tf(v0.y);
                u1.x = f2tf(v1.x); u1.y = f2tf(v1.y);
                *(uint2*)&C[i0] = u0;
                *(uint2*)&C[i1] = u1;
            }
        }
    }
}

// ---------------- tf32 causal flash attention --------------------------------
// Block: 256 queries x one (b,h); 8 warps, each 32 q rows (2 m-tiles of 16).
// Q fragments persistent in registers (zero crossbar in mainloop).
// K/V streamed in 64-key tiles, double-buffered. Fully-masked diagonal tiles
// skipped per-warp (warp-uniform). Scores in exp2 domain (QSCALE folded).
// smem: Q [0,69632)  +  per stage s: K at 69632+s*35840 (272B rows),
//       V at +17408 (288B rows). Total 141312 B.
__global__ __launch_bounds__(256) void attn_tf32(
    const float* __restrict__ Q, const float* __restrict__ K,
    const float* __restrict__ V, float* __restrict__ Ao)
{
    extern __shared__ __align__(16) float smf[];
    const uint32_t sb = smem_to_u32(smf);
    const int qt = gridDim.x - 1 - blockIdx.x;   // heavy blocks first
    const int bh = blockIdx.y;
    const int tid = threadIdx.x;
    const int wid = tid >> 5;
    const int lane = tid & 31;
    const int g = lane >> 2;
    const int t = lane & 3;

    const size_t off = (size_t)bh * NT * HD;
    const float* Qg = Q + off;
    const float* Kg = K + off;
    const float* Vg = V + off;

    auto load_tile = [&](int kt, int s) {
        const uint32_t kb = sb + 69632 + s * 35840;
        const uint32_t vb = kb + 17408;
#pragma unroll
        for (int i = 0; i < 8; i++) {
            const int c = i * 256 + tid;      // 2048 chunks
            const int tile = c >> 10;         // 0:K 1:V
            const int w = c & 1023;
            const int row = w >> 4;
            const int ch = w & 15;
            if (tile == 0)
                cpa16(kb + row * 272 + ch * 16,
                      Kg + (size_t)(kt * 64 + row) * HD + ch * 4);
            else
                cpa16(vb + row * 288 + ch * 16,
                      Vg + (size_t)(kt * 64 + row) * HD + ch * 4);
        }
        asm volatile("cp.async.commit_group;" ::: "memory");
    };

    // ---- stage Q (256 x 64): 4096 chunks ----
#pragma unroll
    for (int i = 0; i < 16; i++) {
        const int c = i * 256 + tid;
        const int row = c >> 4;
        const int ch = c & 15;
        cpa16(sb + row * 272 + ch * 16,
              Qg + (size_t)(qt * 256 + row) * HD + ch * 4);
    }
    asm volatile("cp.async.commit_group;" ::: "memory");

    const int nkt = 4 * qt + 4;
    load_tile(0, 0);
    asm volatile("cp.async.wait_group 1;" ::: "memory");   // Q staged
    __syncthreads();

    // ---- Q fragments to persistent registers ----
    uint32_t qf[2][8][4];
#pragma unroll
    for (int mi = 0; mi < 2; mi++)
#pragma unroll
        for (int kc = 0; kc < 8; kc++) {
            const uint32_t qw = sb + (uint32_t)(32 * wid + 16 * mi + g) * 272
                              + kc * 32 + t * 4;
            qf[mi][kc][0] = lds32(qw);
            qf[mi][kc][1] = lds32(qw + 2176);
            qf[mi][kc][2] = lds32(qw + 16);
            qf[mi][kc][3] = lds32(qw + 2192);
        }

    float O[2][8][4];
#pragma unroll
    for (int mi = 0; mi < 2; mi++)
#pragma unroll
        for (int j = 0; j < 8; j++)
#pragma unroll
            for (int r = 0; r < 4; r++) O[mi][j][r] = 0.0f;
    float mrow[2][2] = {{-3.0e38f, -3.0e38f}, {-3.0e38f, -3.0e38f}};
    float lrow[2][2] = {{0.0f, 0.0f}, {0.0f, 0.0f}};

    const int srcA = (lane & 28) | ((lane & 3) >> 1);
    const int srcB = srcA + 2;
    const bool odd = lane & 1;

    for (int kt = 0; kt < nkt; kt++) {
        const int s = kt & 1;
        if (kt + 1 < nkt) {
            load_tile(kt + 1, s ^ 1);
            asm volatile("cp.async.wait_group 1;" ::: "memory");
        } else {
            asm volatile("cp.async.wait_group 0;" ::: "memory");
        }
        __syncthreads();

        // per-warp skip of fully masked tiles (warp-uniform)
        if (kt * 64 <= qt * 256 + 32 * wid + 31) {
            const uint32_t kb = sb + 69632 + s * 35840;
            const uint32_t vb = kb + 17408;

            // ---- S = Q K^T ----
            float S[2][8][4];
#pragma unroll
            for (int mi = 0; mi < 2; mi++)
#pragma unroll
                for (int j = 0; j < 8; j++)
#pragma unroll
                    for (int r = 0; r < 4; r++) S[mi][j][r] = 0.0f;

#pragma unroll
            for (int kc = 0; kc < 8; kc++)
#pragma unroll
                for (int nj = 0; nj < 8; nj++) {
                    const uint32_t w0 = kb + (uint32_t)(8 * nj + g) * 272
                                      + kc * 32 + t * 4;
                    const uint32_t b0 = lds32(w0);
                    const uint32_t b1 = lds32(w0 + 16);
                    mma_tf32(S[0][nj], qf[0][kc], b0, b1);
                    mma_tf32(S[1][nj], qf[1][kc], b0, b1);
                }

            // ---- causal mask (diagonal region tiles only) ----
            if (kt >= 4 * qt) {
#pragma unroll
                for (int mi = 0; mi < 2; mi++)
#pragma unroll
                    for (int j = 0; j < 8; j++)
#pragma unroll
                        for (int r = 0; r < 4; r++) {
                            const int rq = qt * 256 + 32 * wid + 16 * mi + g
                                         + 8 * (r >> 1);
                            const int ck = kt * 64 + 8 * j + 2 * t + (r & 1);
                            if (ck > rq) S[mi][j][r] = -1.0e30f;
                        }
            }

            // ---- online softmax (exp2 domain) ----
#pragma unroll
            for (int mi = 0; mi < 2; mi++)
#pragma unroll
                for (int gg = 0; gg < 2; gg++) {
                    float mx = -3.0e38f;
#pragma unroll
                    for (int j = 0; j < 8; j++) {
                        mx = fmaxf(mx, S[mi][j][gg * 2]);
                        mx = fmaxf(mx, S[mi][j][gg * 2 + 1]);
                    }
                    mx = fmaxf(mx, __shfl_xor_sync(0xffffffffu, mx, 1));
                    mx = fmaxf(mx, __shfl_xor_sync(0xffffffffu, mx, 2));
                    const float mnew = fmaxf(mrow[mi][gg], mx);
                    const float corr = ex2(mrow[mi][gg] - mnew);
                    mrow[mi][gg] = mnew;
                    float ps = 0.0f;
#pragma unroll
                    for (int j = 0; j < 8; j++) {
                        S[mi][j][gg * 2] = ex2(S[mi][j][gg * 2] - mnew);
                        S[mi][j][gg * 2 + 1] = ex2(S[mi][j][gg * 2 + 1] - mnew);
                        ps += S[mi][j][gg * 2] + S[mi][j][gg * 2 + 1];
                    }
                    ps += __shfl_xor_sync(0xffffffffu, ps, 1);
                    ps += __shfl_xor_sync(0xffffffffu, ps, 2);
                    lrow[mi][gg] = lrow[mi][gg] * corr + ps;
#pragma unroll
                    for (int j = 0; j < 8; j++) {
                        O[mi][j][gg * 2] *= corr;
                        O[mi][j][gg * 2 + 1] *= corr;
                    }
                }

            // ---- O += P V (relayout per mi via shuffles, shared V frags) ----
#pragma unroll
            for (int kc = 0; kc < 8; kc++) {
                uint32_t a0[4], a1[4];
                {
                    const float v00 = __shfl_sync(0xffffffffu, S[0][kc][0], srcA);
                    const float v01 = __shfl_sync(0xffffffffu, S[0][kc][1], srcA);
                    const float v10 = __shfl_sync(0xffffffffu, S[0][kc][2], srcA);
                    const float v11 = __shfl_sync(0xffffffffu, S[0][kc][3], srcA);
                    const float v20 = __shfl_sync(0xffffffffu, S[0][kc][0], srcB);
                    const float v21 = __shfl_sync(0xffffffffu, S[0][kc][1], srcB);
                    const float v30 = __shfl_sync(0xffffffffu, S[0][kc][2], srcB);
                    const float v31 = __shfl_sync(0xffffffffu, S[0][kc][3], srcB);
                    a0[0] = f2tf(odd ? v01 : v00);
                    a0[1] = f2tf(odd ? v11 : v10);
                    a0[2] = f2tf(odd ? v21 : v20);
                    a0[3] = f2tf(odd ? v31 : v30);
                }
                {
                    const float v00 = __shfl_sync(0xffffffffu, S[1][kc][0], srcA);
                    const float v01 = __shfl_sync(0xffffffffu, S[1][kc][1], srcA);
                    const float v10 = __shfl_sync(0xffffffffu, S[1][kc][2], srcA);
                    const float v11 = __shfl_sync(0xffffffffu, S[1][kc][3], srcA);
                    const float v20 = __shfl_sync(0xffffffffu, S[1][kc][0], srcB);
                    const float v21 = __shfl_sync(0xffffffffu, S[1][kc][1], srcB);
                    const float v30 = __shfl_sync(0xffffffffu, S[1][kc][2], srcB);
                    const float v31 = __shfl_sync(0xffffffffu, S[1][kc][3], srcB);
                    a1[0] = f2tf(odd ? v01 : v00);
                    a1[1] = f2tf(odd ? v11 : v10);
                    a1[2] = f2tf(odd ? v21 : v20);
                    a1[3] = f2tf(odd ? v31 : v30);
                }
#pragma unroll
                for (int nj = 0; nj < 8; nj++) {
                    const uint32_t w0 = vb + (uint32_t)(8 * kc + t) * 288
                                      + (uint32_t)(8 * nj + g) * 4;
                    const uint32_t b0 = lds32(w0);
                    const uint32_t b1 = lds32(w0 + 1152);
                    mma_tf32(O[0][nj], a0, b0, b1);
                    mma_tf32(O[1][nj], a1, b0, b1);
                }
            }
        }
        __syncthreads();
    }

    // ---- epilogue: normalize, tf32-round, write [b,t,D] ----
    const int b = bh >> 4, hh = bh & 15;
#pragma unroll
    for (int mi = 0; mi < 2; mi++) {
        const float inv0 = 1.0f / lrow[mi][0];
        const float inv1 = 1.0f / lrow[mi][1];
        const int tq0 = qt * 256 + 32 * wid + 16 * mi + g;
#pragma unroll
        for (int nj = 0; nj < 8; nj++) {
            const int d = hh * 64 + nj * 8 + 2 * t;
            uint2 u0, u1;
            u0.x = f2tf(O[mi][nj][0] * inv0); u0.y = f2tf(O[mi][nj][1] * inv0);
            u1.x = f2tf(O[mi][nj][2] * inv1); u1.y = f2tf(O[mi][nj][3] * inv1);
            *(uint2*)&Ao[((size_t)b * NT + tq0) * ND + d] = u0;
            *(uint2*)&Ao[((size_t)b * NT + tq0 + 8) * ND + d] = u1;
        }
    }
}

// ---------------------------------------------------------------------------
// Inputs (metadata order): x, mask, Wq, bq, Wk, Wv, bv, Wo, bo
// ---------------------------------------------------------------------------
extern "C" void kernel_launch(void* const* d_in, const int* in_sizes, int n_in,
                              void* d_out, int out_size)
{
    const float* x  = (const float*)d_in[0];
    const float* Wq = (const float*)d_in[2];
    const float* bq = (const float*)d_in[3];
    const float* Wk = (const float*)d_in[4];
    const float* Wv = (const float*)d_in[5];
    const float* bv = (const float*)d_in[6];
    const float* Wo = (const float*)d_in[7];
    const float* bo = (const float*)d_in[8];
    float* out = (float*)d_out;

    float *xr, *wqr, *wkr, *wvr, *wor, *qp, *kp, *vp, *aop;
    cudaGetSymbolAddress((void**)&xr, g_xr);
    cudaGetSymbolAddress((void**)&wqr, g_wqr);
    cudaGetSymbolAddress((void**)&wkr, g_wkr);
    cudaGetSymbolAddress((void**)&wvr, g_wvr);
    cudaGetSymbolAddress((void**)&wor, g_wor);
    cudaGetSymbolAddress((void**)&qp, g_q);
    cudaGetSymbolAddress((void**)&kp, g_k);
    cudaGetSymbolAddress((void**)&vp, g_v);
    cudaGetSymbolAddress((void**)&aop, g_ao);

    cudaFuncSetAttribute(gemm_tf32<0>,
                         cudaFuncAttributeMaxDynamicSharedMemorySize, 61440);
    cudaFuncSetAttribute(gemm_tf32<1>,
                         cudaFuncAttributeMaxDynamicSharedMemorySize, 61440);
    cudaFuncSetAttribute(attn_tf32,
                         cudaFuncAttributeMaxDynamicSharedMemorySize, 141312);

    const int M = NB * NT;                 // 8192
    const int xn4 = M * ND / 4;
    const int wn4 = ND * ND / 4;

    tf32_round_kernel<<<(xn4 + 255) / 256, 256>>>(x, xr, xn4);
    tf32_round_kernel<<<(wn4 + 255) / 256, 256>>>(Wq, wqr, wn4);
    tf32_round_kernel<<<(wn4 + 255) / 256, 256>>>(Wk, wkr, wn4);
    tf32_round_kernel<<<(wn4 + 255) / 256, 256>>>(Wv, wvr, wn4);
    tf32_round_kernel<<<(wn4 + 255) / 256, 256>>>(Wo, wor, wn4);

    dim3 gemm_grid(ND / 128, M / 256);     // (8, 32) = 256 CTAs
    gemm_tf32<1><<<gemm_grid, 256, 61440>>>(xr, wqr, bq, QSCALE, qp);
    gemm_tf32<1><<<gemm_grid, 256, 61440>>>(xr, wkr, nullptr, 1.0f, kp);
    gemm_tf32<1><<<gemm_grid, 256, 61440>>>(xr, wvr, bv, 1.0f, vp);

    attn_tf32<<<dim3(NT / 256, NB * NH), 256, 141312>>>(qp, kp, vp, aop);

    gemm_tf32<0><<<gemm_grid, 256, 61440>>>(aop, wor, bo, 1.0f, out);
}

// round 13
// speedup vs baseline: 9.5000x; 1.6217x over previous
#include <cuda_runtime.h>
#include <cuda_fp16.h>
#include <cstdint>

#define NB 8
#define NT 1024
#define ND 1024
#define NH 16
#define HD 64
// hd^-0.5 * log2(e), folded into Q projection output (exp2-domain softmax)
#define QSCALE 0.1803368801111243f

// ---------------- scratch (device globals; no allocation allowed) ----------
__device__ __half g_xh[NB * NT * ND];
__device__ __half g_wqh[ND * ND], g_wkh[ND * ND], g_wvh[ND * ND], g_woh[ND * ND];
__device__ __half g_q[NB * NH * NT * HD], g_k[NB * NH * NT * HD];
__device__ __half g_vt[NB * NH * HD * NT];         // [b,h,d,t]
__device__ __half g_oh[NB * NT * ND];

// ---------------- helpers ---------------------------------------------------
__device__ __forceinline__ uint32_t smem_to_u32(const void* p) {
    uint32_t a;
    asm("{ .reg .u64 t; cvta.to.shared.u64 t, %1; cvt.u32.u64 %0, t; }"
        : "=r"(a) : "l"(p));
    return a;
}
__device__ __forceinline__ void ldsm4(uint32_t* r, uint32_t addr) {
    asm volatile("ldmatrix.sync.aligned.m8n8.x4.shared.b16 {%0,%1,%2,%3}, [%4];"
                 : "=r"(r[0]), "=r"(r[1]), "=r"(r[2]), "=r"(r[3]) : "r"(addr));
}
__device__ __forceinline__ void mma_f16(float* d, const uint32_t* a,
                                        uint32_t b0, uint32_t b1) {
    asm volatile(
        "mma.sync.aligned.m16n8k16.row.col.f32.f16.f16.f32 "
        "{%0,%1,%2,%3}, {%4,%5,%6,%7}, {%8,%9}, {%0,%1,%2,%3};"
        : "+f"(d[0]), "+f"(d[1]), "+f"(d[2]), "+f"(d[3])
        : "r"(a[0]), "r"(a[1]), "r"(a[2]), "r"(a[3]), "r"(b0), "r"(b1));
}
__device__ __forceinline__ void cpa16(uint32_t dst, const void* gsrc) {
    asm volatile("cp.async.cg.shared.global [%0], [%1], 16;"
                 :: "r"(dst), "l"(__cvta_generic_to_global(gsrc)) : "memory");
}
__device__ __forceinline__ uint32_t sw128(uint32_t off) {
    return off ^ ((off >> 3) & 0x70);
}
__device__ __forceinline__ uint32_t pack2h(float a, float b) {
    __half2 h = __floats2half2_rn(a, b);
    return *reinterpret_cast<uint32_t*>(&h);
}
__device__ __forceinline__ float ex2(float x) {
    float r;
    asm("ex2.approx.f32 %0, %1;" : "=f"(r) : "f"(x));
    return r;
}

// ---------------- fp32 -> fp16 conversion ------------------------------------
__global__ __launch_bounds__(256) void toh_kernel(
    const float* __restrict__ src, __half* __restrict__ dst, int n4)
{
    int i = blockIdx.x * 256 + threadIdx.x;
    if (i >= n4) return;
    float4 v = ((const float4*)src)[i];
    uint2 o;
    o.x = pack2h(v.x, v.y);
    o.y = pack2h(v.z, v.w);
    ((uint2*)dst)[i] = o;
}

// ---------------- fp16 single-pass GEMM --------------------------------------
// C[m,n] = sum_k A[m,k]*W[n,k]; CTA 256x128, 8 warps (4m x 2n), warp 64x64,
// k-step 16, double-buffered cp.async. Rows padded to 48B (stride-48 proven
// conflict-free for ldmatrix).
// MODE 0: output GEMM -> fp32 [M,ND] + bias_o.
// MODE 1: fused QKV over N=3072; region per block: 0=Q(head-major fp16,
//         bias+QSCALE), 1=K(head-major fp16), 2=V([b,h,d,t] fp16, bias).
template <int MODE>
__global__ __launch_bounds__(256, 1) void gemm_f16(
    const __half* __restrict__ A,
    const __half* __restrict__ W0, const __half* __restrict__ W1,
    const __half* __restrict__ W2,
    const float* __restrict__ bias_q, const float* __restrict__ bias_v,
    const float* __restrict__ bias_o, float* __restrict__ Cf,
    __half* __restrict__ Qo, __half* __restrict__ Ko, __half* __restrict__ Vt)
{
    extern __shared__ __align__(16) char smemc[];
    const uint32_t sb = smem_to_u32(smemc);
    const int tid = threadIdx.x;
    const int wid = tid >> 5;
    const int lane = tid & 31;
    const int g = lane >> 2;
    const int t = lane & 3;
    const int m0 = (wid >> 1) * 64;
    const int n0 = (wid & 1) * 64;
    const int brow = blockIdx.y * 256;
    const int bcol = blockIdx.x * 128;

    int region = 0;
    const __half* B = W0;
    if (MODE == 1) {
        region = bcol >> 10;
        B = (region == 0) ? W0 : (region == 1 ? W1 : W2);
    }
    const int bn = bcol & 1023;

    float acc[4][8][4];
#pragma unroll
    for (int i = 0; i < 4; i++)
#pragma unroll
        for (int j = 0; j < 8; j++)
#pragma unroll
            for (int r = 0; r < 4; r++) acc[i][j][r] = 0.0f;

    // stage: A 256 rows x 48B @0 (data 32B/row); B 128 x 48B @12288; stride 18432
    auto load_stage = [&](int s, int kt) {
#pragma unroll
        for (int i = 0; i < 3; i++) {
            const int c = i * 256 + tid;          // 768 chunks of 16B
            uint32_t dst;
            const __half* src;
            if (c < 512) {                        // A: 256 rows x 2 chunks
                const int row = c >> 1, ch = c & 1;
                dst = sb + s * 18432 + row * 48 + ch * 16;
                src = A + (size_t)(brow + row) * ND + kt * 16 + ch * 8;
            } else {                              // B: 128 rows x 2 chunks
                const int w = c - 512;
                const int row = w >> 1, ch = w & 1;
                dst = sb + s * 18432 + 12288 + row * 48 + ch * 16;
                src = B + (size_t)(bn + row) * ND + kt * 16 + ch * 8;
            }
            cpa16(dst, src);
        }
        asm volatile("cp.async.commit_group;" ::: "memory");
    };

    load_stage(0, 0);

    const uint32_t a_row = lane & 15;
    const uint32_t a_coff = (lane >> 4) << 4;
    const uint32_t b_row = (lane & 7) + (((lane >> 4) & 1) << 3);
    const uint32_t b_coff = ((lane >> 3) & 1) << 4;

    for (int kt = 0; kt < 64; kt++) {
        const int s = kt & 1;
        if (kt + 1 < 64) {
            load_stage(s ^ 1, kt + 1);
            asm volatile("cp.async.wait_group 1;" ::: "memory");
        } else {
            asm volatile("cp.async.wait_group 0;" ::: "memory");
        }
        __syncthreads();

        const uint32_t base = sb + s * 18432;
        uint32_t a[4][4], b[4][4];
#pragma unroll
        for (int mi = 0; mi < 4; mi++)
            ldsm4(a[mi], base + (m0 + 16 * mi + a_row) * 48 + a_coff);
#pragma unroll
        for (int nj = 0; nj < 4; nj++)
            ldsm4(b[nj], base + 12288 + (n0 + 16 * nj + b_row) * 48 + b_coff);
#pragma unroll
        for (int mi = 0; mi < 4; mi++)
#pragma unroll
            for (int oct = 0; oct < 8; oct++) {
                const int j = oct >> 1, r = (oct & 1) * 2;
                mma_f16(acc[mi][oct], a[mi], b[j][r], b[j][r + 1]);
            }
        __syncthreads();
    }

#pragma unroll
    for (int mi = 0; mi < 4; mi++) {
#pragma unroll
        for (int oct = 0; oct < 8; oct++) {
            const int mA = brow + m0 + 16 * mi + g;   // mA+8 stays in-batch
            const int c = n0 + 8 * oct + 2 * t;
            float2 v0, v1;
            v0.x = acc[mi][oct][0]; v0.y = acc[mi][oct][1];
            v1.x = acc[mi][oct][2]; v1.y = acc[mi][oct][3];
            if (MODE == 0) {
                const int n = bcol + c;
                const float2 bv = *(const float2*)(bias_o + n);
                v0.x += bv.x; v0.y += bv.y;
                v1.x += bv.x; v1.y += bv.y;
                *(float2*)&Cf[(size_t)mA * ND + n] = v0;
                *(float2*)&Cf[(size_t)(mA + 8) * ND + n] = v1;
            } else {
                const int nn = bn + c;
                const int hh = nn >> 6, d = nn & 63;
                const int b0_ = mA >> 10, t0 = mA & 1023;
                if (region == 0) {
                    const float2 bv = *(const float2*)(bias_q + nn);
                    v0.x = (v0.x + bv.x) * QSCALE; v0.y = (v0.y + bv.y) * QSCALE;
                    v1.x = (v1.x + bv.x) * QSCALE; v1.y = (v1.y + bv.y) * QSCALE;
                    const size_t i0 = (((size_t)(b0_ * NH + hh) * NT + t0) << 6) + d;
                    *(uint32_t*)&Qo[i0] = pack2h(v0.x, v0.y);
                    *(uint32_t*)&Qo[i0 + (8 << 6)] = pack2h(v1.x, v1.y);
                } else if (region == 1) {
                    const size_t i0 = (((size_t)(b0_ * NH + hh) * NT + t0) << 6) + d;
                    *(uint32_t*)&Ko[i0] = pack2h(v0.x, v0.y);
                    *(uint32_t*)&Ko[i0 + (8 << 6)] = pack2h(v1.x, v1.y);
                } else {
                    const float2 bv = *(const float2*)(bias_v + nn);
                    v0.x += bv.x; v0.y += bv.y;
                    v1.x += bv.x; v1.y += bv.y;
                    const size_t vbase = ((size_t)(b0_ * NH + hh) * HD + d) * NT;
                    Vt[vbase + t0] = __float2half_rn(v0.x);
                    Vt[vbase + NT + t0] = __float2half_rn(v0.y);
                    Vt[vbase + t0 + 8] = __float2half_rn(v1.x);
                    Vt[vbase + NT + t0 + 8] = __float2half_rn(v1.y);
                }
            }
        }
    }
}

// ---------------- fp16 causal flash attention --------------------------------
// Block: 256 queries x one (b,h); 8 warps x 32 q rows. Q frags persistent in
// registers; K/V in 64-key sw128 tiles, double-buffered; fully masked diagonal
// tiles skipped per warp. Scores in exp2 domain (QSCALE folded into Q).
// smem: Q [0,32768); stage s: K @32768+s*16384, V @+8192. Total 65536 B.
__global__ __launch_bounds__(256, 1) void attn_f16(
    const __half* __restrict__ Q, const __half* __restrict__ K,
    const __half* __restrict__ Vt, __half* __restrict__ O)
{
    extern __shared__ __align__(16) char smemc[];
    const uint32_t sb = smem_to_u32(smemc);
    const int qt = gridDim.x - 1 - blockIdx.x;   // heavy blocks first
    const int bh = blockIdx.y;
    const int tid = threadIdx.x;
    const int wid = tid >> 5;
    const int lane = tid & 31;
    const int g = lane >> 2;
    const int t = lane & 3;

    const size_t off = (size_t)bh * NT * HD;     // same count for Vt [b,h,d,t]

    auto load_tile = [&](int kt, int s) {
        const uint32_t kb = sb + 32768 + s * 16384;
        const uint32_t vb = kb + 8192;
#pragma unroll
        for (int i = 0; i < 4; i++) {
            const int c = i * 256 + tid;          // 1024 chunks
            const int tile = c >> 9;              // 0:K 1:V
            const int w = c & 511;
            const int row = w >> 3;
            const int ch = w & 7;
            if (tile == 0)
                cpa16(kb + sw128(row * 128 + ch * 16),
                      K + off + (size_t)(kt * 64 + row) * HD + ch * 8);
            else
                cpa16(vb + sw128(row * 128 + ch * 16),
                      Vt + off + (size_t)row * NT + kt * 64 + ch * 8);
        }
        asm volatile("cp.async.commit_group;" ::: "memory");
    };

    // stage Q (256 x 64 halves): 2048 chunks
#pragma unroll
    for (int i = 0; i < 8; i++) {
        const int c = i * 256 + tid;
        const int row = c >> 3;
        const int ch = c & 7;
        cpa16(sb + sw128(row * 128 + ch * 16),
              Q + off + (size_t)(qt * 256 + row) * HD + ch * 8);
    }
    asm volatile("cp.async.commit_group;" ::: "memory");

    const int nkt = 4 * qt + 4;
    load_tile(0, 0);
    asm volatile("cp.async.wait_group 1;" ::: "memory");   // Q staged
    __syncthreads();

    const uint32_t a_row = lane & 15;
    const uint32_t a_coff = (lane >> 4) << 4;
    const uint32_t b_row = (lane & 7) + (((lane >> 4) & 1) << 3);
    const uint32_t b_coff = ((lane >> 3) & 1) << 4;

    // persistent Q fragments: 2 m-tiles x 4 k-chunks
    uint32_t qf[2][4][4];
#pragma unroll
    for (int mi = 0; mi < 2; mi++)
#pragma unroll
        for (int kc = 0; kc < 4; kc++)
            ldsm4(qf[mi][kc],
                  sb + sw128((32 * wid + 16 * mi + a_row) * 128 + kc * 32 + a_coff));

    float Oa[2][8][4];
#pragma unroll
    for (int mi = 0; mi < 2; mi++)
#pragma unroll
        for (int j = 0; j < 8; j++)
#pragma unroll
            for (int r = 0; r < 4; r++) Oa[mi][j][r] = 0.0f;
    float mrow[2][2] = {{-3.0e38f, -3.0e38f}, {-3.0e38f, -3.0e38f}};
    float lrow[2][2] = {{0.0f, 0.0f}, {0.0f, 0.0f}};

    for (int kt = 0; kt < nkt; kt++) {
        const int s = kt & 1;
        if (kt + 1 < nkt) {
            load_tile(kt + 1, s ^ 1);
            asm volatile("cp.async.wait_group 1;" ::: "memory");
        } else {
            asm volatile("cp.async.wait_group 0;" ::: "memory");
        }
        __syncthreads();

        if (kt * 64 <= qt * 256 + 32 * wid + 31) {   // warp-uniform causal skip
            const uint32_t kb = sb + 32768 + s * 16384;
            const uint32_t vb = kb + 8192;

            // ---- S = Q K^T ----
            float S[2][8][4];
#pragma unroll
            for (int mi = 0; mi < 2; mi++)
#pragma unroll
                for (int j = 0; j < 8; j++)
#pragma unroll
                    for (int r = 0; r < 4; r++) S[mi][j][r] = 0.0f;

#pragma unroll
            for (int kc = 0; kc < 4; kc++) {
                uint32_t bK[4][4];
#pragma unroll
                for (int nj = 0; nj < 4; nj++)
                    ldsm4(bK[nj],
                          kb + sw128((16 * nj + b_row) * 128 + kc * 32 + b_coff));
#pragma unroll
                for (int oct = 0; oct < 8; oct++) {
                    const int j = oct >> 1, r = (oct & 1) * 2;
                    mma_f16(S[0][oct], qf[0][kc], bK[j][r], bK[j][r + 1]);
                    mma_f16(S[1][oct], qf[1][kc], bK[j][r], bK[j][r + 1]);
                }
            }

            // ---- causal mask (diagonal region only) ----
            if (kt >= 4 * qt) {
#pragma unroll
                for (int mi = 0; mi < 2; mi++)
#pragma unroll
                    for (int j = 0; j < 8; j++)
#pragma unroll
                        for (int r = 0; r < 4; r++) {
                            const int rq = qt * 256 + 32 * wid + 16 * mi + g
                                         + 8 * (r >> 1);
                            const int ck = kt * 64 + 8 * j + 2 * t + (r & 1);
                            if (ck > rq) S[mi][j][r] = -1.0e30f;
                        }
            }

            // ---- online softmax (exp2 domain) ----
#pragma unroll
            for (int mi = 0; mi < 2; mi++)
#pragma unroll
                for (int gg = 0; gg < 2; gg++) {
                    float mx = -3.0e38f;
#pragma unroll
                    for (int j = 0; j < 8; j++) {
                        mx = fmaxf(mx, S[mi][j][gg * 2]);
                        mx = fmaxf(mx, S[mi][j][gg * 2 + 1]);
                    }
                    mx = fmaxf(mx, __shfl_xor_sync(0xffffffffu, mx, 1));
                    mx = fmaxf(mx, __shfl_xor_sync(0xffffffffu, mx, 2));
                    const float mnew = fmaxf(mrow[mi][gg], mx);
                    const float corr = ex2(mrow[mi][gg] - mnew);
                    mrow[mi][gg] = mnew;
                    float ps = 0.0f;
#pragma unroll
                    for (int j = 0; j < 8; j++) {
                        S[mi][j][gg * 2] = ex2(S[mi][j][gg * 2] - mnew);
                        S[mi][j][gg * 2 + 1] = ex2(S[mi][j][gg * 2 + 1] - mnew);
                        ps += S[mi][j][gg * 2] + S[mi][j][gg * 2 + 1];
                    }
                    ps += __shfl_xor_sync(0xffffffffu, ps, 1);
                    ps += __shfl_xor_sync(0xffffffffu, ps, 2);
                    lrow[mi][gg] = lrow[mi][gg] * corr + ps;
#pragma unroll
                    for (int j = 0; j < 8; j++) {
                        Oa[mi][j][gg * 2] *= corr;
                        Oa[mi][j][gg * 2 + 1] *= corr;
                    }
                }

            // ---- O += P V : C-frag pairs pack directly into fp16 A-frags ----
#pragma unroll
            for (int kc = 0; kc < 4; kc++) {
                uint32_t bV[4][4];
#pragma unroll
                for (int nj = 0; nj < 4; nj++)
                    ldsm4(bV[nj],
                          vb + sw128((16 * nj + b_row) * 128 + kc * 32 + b_coff));
#pragma unroll
                for (int mi = 0; mi < 2; mi++) {
                    uint32_t aP[4];
                    aP[0] = pack2h(S[mi][2 * kc][0], S[mi][2 * kc][1]);
                    aP[1] = pack2h(S[mi][2 * kc][2], S[mi][2 * kc][3]);
                    aP[2] = pack2h(S[mi][2 * kc + 1][0], S[mi][2 * kc + 1][1]);
                    aP[3] = pack2h(S[mi][2 * kc + 1][2], S[mi][2 * kc + 1][3]);
#pragma unroll
                    for (int oct = 0; oct < 8; oct++) {
                        const int j = oct >> 1, r = (oct & 1) * 2;
                        mma_f16(Oa[mi][oct], aP, bV[j][r], bV[j][r + 1]);
                    }
                }
            }
        }
        __syncthreads();
    }

    // ---- epilogue: normalize, fp16-pack, write [b,t,D] ----
    const int b = bh >> 4, hh = bh & 15;
#pragma unroll
    for (int mi = 0; mi < 2; mi++) {
        const float inv0 = 1.0f / lrow[mi][0];
        const float inv1 = 1.0f / lrow[mi][1];
        const int tq0 = qt * 256 + 32 * wid + 16 * mi + g;
#pragma unroll
        for (int oct = 0; oct < 8; oct++) {
            const int d = hh * 64 + 8 * oct + 2 * t;
            *(uint32_t*)&O[((size_t)b * NT + tq0) * ND + d] =
                pack2h(Oa[mi][oct][0] * inv0, Oa[mi][oct][1] * inv0);
            *(uint32_t*)&O[((size_t)b * NT + tq0 + 8) * ND + d] =
                pack2h(Oa[mi][oct][2] * inv1, Oa[mi][oct][3] * inv1);
        }
    }
}

// ---------------------------------------------------------------------------
// Inputs (metadata order): x, mask, Wq, bq, Wk, Wv, bv, Wo, bo
// ---------------------------------------------------------------------------
extern "C" void kernel_launch(void* const* d_in, const int* in_sizes, int n_in,
                              void* d_out, int out_size)
{
    const float* x  = (const float*)d_in[0];
    const float* Wq = (const float*)d_in[2];
    const float* bq = (const float*)d_in[3];
    const float* Wk = (const float*)d_in[4];
    const float* Wv = (const float*)d_in[5];
    const float* bv = (const float*)d_in[6];
    const float* Wo = (const float*)d_in[7];
    const float* bo = (const float*)d_in[8];
    float* out = (float*)d_out;

    __half *xh, *wqh, *wkh, *wvh, *woh, *qp, *kp, *vtp, *ohp;
    cudaGetSymbolAddress((void**)&xh, g_xh);
    cudaGetSymbolAddress((void**)&wqh, g_wqh);
    cudaGetSymbolAddress((void**)&wkh, g_wkh);
    cudaGetSymbolAddress((void**)&wvh, g_wvh);
    cudaGetSymbolAddress((void**)&woh, g_woh);
    cudaGetSymbolAddress((void**)&qp, g_q);
    cudaGetSymbolAddress((void**)&kp, g_k);
    cudaGetSymbolAddress((void**)&vtp, g_vt);
    cudaGetSymbolAddress((void**)&ohp, g_oh);

    cudaFuncSetAttribute(gemm_f16<0>,
                         cudaFuncAttributeMaxDynamicSharedMemorySize, 36864);
    cudaFuncSetAttribute(gemm_f16<1>,
                         cudaFuncAttributeMaxDynamicSharedMemorySize, 36864);
    cudaFuncSetAttribute(attn_f16,
                         cudaFuncAttributeMaxDynamicSharedMemorySize, 65536);

    const int M = NB * NT;                 // 8192
    const int xn4 = M * ND / 4;            // 2M
    const int wn4 = ND * ND / 4;           // 256K

    toh_kernel<<<(xn4 + 255) / 256, 256>>>(x, xh, xn4);
    toh_kernel<<<(wn4 + 255) / 256, 256>>>(Wq, wqh, wn4);
    toh_kernel<<<(wn4 + 255) / 256, 256>>>(Wk, wkh, wn4);
    toh_kernel<<<(wn4 + 255) / 256, 256>>>(Wv, wvh, wn4);
    toh_kernel<<<(wn4 + 255) / 256, 256>>>(Wo, woh, wn4);

    // fused QKV projection: N = 3072, region selected per block
    gemm_f16<1><<<dim3(3 * ND / 128, M / 256), 256, 36864>>>(
        xh, wqh, wkh, wvh, bq, bv, nullptr, nullptr, qp, kp, vtp);

    attn_f16<<<dim3(NT / 256, NB * NH), 256, 65536>>>(qp, kp, vtp, ohp);

    // output projection
    gemm_f16<0><<<dim3(ND / 128, M / 256), 256, 36864>>>(
        ohp, woh, nullptr, nullptr, nullptr, nullptr, bo, out,
        nullptr, nullptr, nullptr);
}